// round 7
// baseline (speedup 1.0000x reference)
#include <cuda_runtime.h>
#include <cuda_bf16.h>
#include <cuda_fp16.h>
#include <math.h>
#include <stdint.h>

// Problem constants
#define BB 2048          // batch
#define NN 4096          // 2*B rows of z
#define DD 512           // half feature dim
#define NHALF 12         // 6 inputs x 2 halves
#define NLOSS 9          // contrastive losses
#define NORTHO 12        // ortho pairs
#define TINV 5.0f        // 1/temperature
// sqrt(TINV * log2(e)) folded into operands => acc = sim*TINV*log2e
#define SCALE_K  2.6857913787767947f
#define SCALE_K2 7.2134752044448170f   // TINV*log2(e)
#define LN2      0.6931471805599453f

// Scratch (device globals; no allocation allowed)
__device__ __nv_bfloat16 g_zhi[NHALF * BB * DD];   // bf16 normalized * SCALE_K (aux dots)
__device__ uint8_t       g_z8 [NHALF * BB * DD];   // e4m3 normalized * SCALE_K (MMA)
__device__ float         g_rowsum[NLOSS * NN];     // per-row sum of exp(sim/T)

__constant__ int c_cpA[NLOSS] = {0, 0, 2, 6, 6,  8, 1, 3, 5};
__constant__ int c_cpB[NLOSS] = {2, 4, 4, 8, 10, 10, 7, 9, 11};
__constant__ int c_opA[NORTHO] = {0, 2, 4, 1, 1, 3, 6, 8, 10, 7, 7, 9};
__constant__ int c_opB[NORTHO] = {1, 3, 5, 3, 5, 5, 7, 9, 11, 9, 11, 11};

// ---------------------------------------------------------------------------
__device__ __forceinline__ uint32_t smem_u32(const void* p) {
    uint32_t a;
    asm("{ .reg .u64 t; cvta.to.shared.u64 t, %1; cvt.u32.u64 %0, t; }" : "=r"(a) : "l"(p));
    return a;
}
__device__ __forceinline__ void cpasync16(uint32_t dst, const void* src) {
    asm volatile("cp.async.cg.shared.global [%0], [%1], 16;" :: "r"(dst), "l"(src));
}
__device__ __forceinline__ void ldsm4(uint32_t* r, uint32_t addr) {
    asm volatile("ldmatrix.sync.aligned.m8n8.x4.shared.b16 {%0,%1,%2,%3}, [%4];"
                 : "=r"(r[0]), "=r"(r[1]), "=r"(r[2]), "=r"(r[3]) : "r"(addr));
}
// fp8 e4m3 MMA, K=32: fragments are byte-identical to bf16 m16n8k16 fragments.
__device__ __forceinline__ void mma16832(float* d, const uint32_t* a,
                                         uint32_t b0, uint32_t b1) {
    asm volatile(
        "mma.sync.aligned.m16n8k32.row.col.f32.e4m3.e4m3.f32 "
        "{%0,%1,%2,%3}, {%4,%5,%6,%7}, {%8,%9}, {%0,%1,%2,%3};"
        : "+f"(d[0]), "+f"(d[1]), "+f"(d[2]), "+f"(d[3])
        : "r"(a[0]), "r"(a[1]), "r"(a[2]), "r"(a[3]), "r"(b0), "r"(b1));
}
__device__ __forceinline__ float ex2f(float x) {
    float r;
    asm("ex2.approx.f32 %0, %1;" : "=f"(r) : "f"(x));
    return r;
}
__device__ __forceinline__ uint16_t cvt_e4m3x2(float hi, float lo) {
    uint16_t r;
    asm("cvt.rn.satfinite.e4m3x2.f32 %0, %1, %2;" : "=h"(r) : "f"(hi), "f"(lo));
    return r;
}
// bf16 row dot product (16 elems/lane, warp-reduced). Returns scaled dot.
__device__ __forceinline__ float bf16_row_dot(const __nv_bfloat16* a,
                                              const __nv_bfloat16* b, int lane) {
    uint4 xa = reinterpret_cast<const uint4*>(a)[lane];
    uint4 xb = reinterpret_cast<const uint4*>(b)[lane];
    const __nv_bfloat162* pa = reinterpret_cast<const __nv_bfloat162*>(&xa);
    const __nv_bfloat162* pb = reinterpret_cast<const __nv_bfloat162*>(&xb);
    float d = 0.0f;
#pragma unroll
    for (int i = 0; i < 8; i++) {
        float2 fa = __bfloat1622float2(pa[i]);
        float2 fb = __bfloat1622float2(pb[i]);
        d += fa.x * fb.x + fa.y * fb.y;
    }
#pragma unroll
    for (int o = 16; o; o >>= 1) d += __shfl_xor_sync(0xFFFFFFFFu, d, o);
    return d;
}

// ---------------------------------------------------------------------------
// 0) zero rowsums + output scalar
// ---------------------------------------------------------------------------
__global__ void zero_kernel(float* out) {
    int i = blockIdx.x * blockDim.x + threadIdx.x;
    if (i < NLOSS * NN) g_rowsum[i] = 0.0f;
    if (i == 0) out[0] = 0.0f;
}

// ---------------------------------------------------------------------------
// 1) row-normalize all 12 halves; emit scaled bf16 + scaled e4m3. One warp/row.
// ---------------------------------------------------------------------------
__global__ void norm_kernel(const float* __restrict__ i0, const float* __restrict__ i1,
                            const float* __restrict__ i2, const float* __restrict__ i3,
                            const float* __restrict__ i4, const float* __restrict__ i5) {
    int gw   = (blockIdx.x * blockDim.x + threadIdx.x) >> 5;
    int lane = threadIdx.x & 31;
    if (gw >= NHALF * BB) return;
    int h = gw / BB;
    int r = gw % BB;
    int m = h >> 1;
    const float* base = (m == 0) ? i0 : (m == 1) ? i1 : (m == 2) ? i2
                       : (m == 3) ? i3 : (m == 4) ? i4 : i5;
    const float* src = base + (size_t)r * 1024 + (size_t)(h & 1) * 512;

    float4 v[4];
    float ss = 0.0f;
#pragma unroll
    for (int w = 0; w < 4; w++) {
        v[w] = reinterpret_cast<const float4*>(src)[lane + w * 32];
        ss += v[w].x * v[w].x + v[w].y * v[w].y + v[w].z * v[w].z + v[w].w * v[w].w;
    }
#pragma unroll
    for (int o = 16; o; o >>= 1) ss += __shfl_xor_sync(0xFFFFFFFFu, ss, o);
    float invk = SCALE_K / fmaxf(sqrtf(ss), 1e-8f);

    size_t rowoff = (size_t)h * BB * DD + (size_t)r * DD;
    __nv_bfloat162* dhi = reinterpret_cast<__nv_bfloat162*>(g_zhi + rowoff);
    uint32_t*       d8  = reinterpret_cast<uint32_t*>(g_z8 + rowoff);
#pragma unroll
    for (int w = 0; w < 4; w++) {
        float ax = v[w].x * invk, ay = v[w].y * invk;
        float az = v[w].z * invk, aw = v[w].w * invk;
        int pi = (lane + w * 32) * 2;
        dhi[pi]     = __floats2bfloat162_rn(ax, ay);
        dhi[pi + 1] = __floats2bfloat162_rn(az, aw);
        uint32_t p01 = cvt_e4m3x2(ay, ax);
        uint32_t p23 = cvt_e4m3x2(aw, az);
        d8[lane + w * 32] = p01 | (p23 << 16);
    }
}

// ---------------------------------------------------------------------------
// 2) fp8 MMA tile kernel: 128x128 sim tile, ex2 epilogue (acc pre-scaled).
//    Grid: x = 528 upper-triangle tiles, y = loss. 256 threads, 8 warps.
//    Warp tile 64x32. 4 K-chunks of 128 fp8 (128B rows), 3-stage cp.async,
//    occ 2, one __syncthreads per chunk.
// ---------------------------------------------------------------------------
#define KCHUNK 128            // fp8 elements per chunk (=128 bytes)
#define NCHUNK 4
#define BUFSZ  16384          // 128 rows * 128 bytes
#define STAGE  32768          // A + B buffer per stage
#define NSTG   3
#define SWZOFF(row, seg) ((uint32_t)((row) * 128 + (((seg) ^ ((row) & 7)) << 4)))

__global__ __launch_bounds__(256, 2) void ctile_kernel() {
    extern __shared__ unsigned char smem[];
    const int loss = blockIdx.y;
    int t = blockIdx.x;
    int bi = 0;
    while (t >= 32 - bi) { t -= 32 - bi; bi++; }
    const int bj = bi + t;
    const int r0 = bi * 128, c0 = bj * 128;
    const bool diag = (bi == bj);
    const int tid = threadIdx.x, wid = tid >> 5, lane = tid & 31;
    const int wm = wid & 1, wn = wid >> 1;

    const uint8_t* ZA = g_z8 + (size_t)c_cpA[loss] * BB * DD;
    const uint8_t* ZB = g_z8 + (size_t)c_cpB[loss] * BB * DD;
    const uint8_t* sA = (r0 < BB) ? ZA + (size_t)r0 * DD : ZB + (size_t)(r0 - BB) * DD;
    const uint8_t* sB = (c0 < BB) ? ZA + (size_t)c0 * DD : ZB + (size_t)(c0 - BB) * DD;

    const uint32_t sbase = smem_u32(smem);

    float acc[4][4][4];
#pragma unroll
    for (int s = 0; s < 4; s++)
#pragma unroll
        for (int j = 0; j < 4; j++)
#pragma unroll
            for (int g = 0; g < 4; g++) acc[s][j][g] = 0.0f;

    // ---- prologue: prefetch chunks 0 and 1 into stages 0,1 ----
#pragma unroll
    for (int pc = 0; pc < 2; pc++) {
        const int kc = pc * KCHUNK;
        const uint32_t dbuf = sbase + pc * STAGE;
#pragma unroll
        for (int q = tid; q < 1024; q += 256) {
            int row = q >> 3, seg = q & 7;
            uint32_t off = SWZOFF(row, seg);
            cpasync16(dbuf + off,         sA + (size_t)row * DD + kc + seg * 16);
            cpasync16(dbuf + BUFSZ + off, sB + (size_t)row * DD + kc + seg * 16);
        }
        asm volatile("cp.async.commit_group;" ::: "memory");
    }

    uint32_t stg = 0;   // stage index of chunk c
    for (int c = 0; c < NCHUNK; c++) {
        if (c < NCHUNK - 1) {
            asm volatile("cp.async.wait_group 1;" ::: "memory");
        } else {
            asm volatile("cp.async.wait_group 0;" ::: "memory");
        }
        __syncthreads();   // stage c visible; reads of stage c-1 done

        if (c < NCHUNK - 2) {
            const int kc = (c + 2) * KCHUNK;
            uint32_t ds = stg + 2; if (ds >= NSTG) ds -= NSTG;
            const uint32_t dbuf = sbase + ds * STAGE;
#pragma unroll
            for (int q = tid; q < 1024; q += 256) {
                int row = q >> 3, seg = q & 7;
                uint32_t off = SWZOFF(row, seg);
                cpasync16(dbuf + off,         sA + (size_t)row * DD + kc + seg * 16);
                cpasync16(dbuf + BUFSZ + off, sB + (size_t)row * DD + kc + seg * 16);
            }
            asm volatile("cp.async.commit_group;" ::: "memory");
        }

        const uint32_t ab = sbase + stg * STAGE;
        const uint32_t bb = ab + BUFSZ;
#pragma unroll
        for (int kb = 0; kb < 4; kb++) {     // each kb = K=32 fp8 (32 bytes)
            uint32_t af[4][4], bf[2][4];
#pragma unroll
            for (int s = 0; s < 4; s++) {
                int row = wm * 64 + s * 16 + (lane & 15);
                int seg = kb * 2 + (lane >> 4);
                ldsm4(af[s], ab + SWZOFF(row, seg));
            }
#pragma unroll
            for (int p = 0; p < 2; p++) {
                int row = wn * 32 + p * 16 + (lane & 7) + ((lane >> 4) << 3);
                int seg = kb * 2 + ((lane >> 3) & 1);
                ldsm4(bf[p], bb + SWZOFF(row, seg));
            }
#pragma unroll
            for (int s = 0; s < 4; s++)
#pragma unroll
                for (int j = 0; j < 4; j++)
                    mma16832(acc[s][j], af[s], bf[j >> 1][(j & 1) * 2],
                             bf[j >> 1][(j & 1) * 2 + 1]);
        }
        if (++stg >= NSTG) stg = 0;
    }

    // --------------------------- epilogue ---------------------------
    // acc == sim * TINV * log2(e); exp(sim/T) = ex2(acc)
    const int rl  = lane >> 2;          // row within 8-group
    const int cl2 = (lane & 3) * 2;     // col pair base

    float rp[8], cp[8];

    if (!diag) {
        __half2 rs01[4], rs23[4], csm[4];
#pragma unroll
        for (int i = 0; i < 4; i++) {
            rs01[i] = __float2half2_rn(0.0f);
            rs23[i] = __float2half2_rn(0.0f);
            csm[i]  = __float2half2_rn(0.0f);
        }
#pragma unroll
        for (int s = 0; s < 4; s++)
#pragma unroll
            for (int j = 0; j < 4; j++) {
                __half2 e01 = h2exp2(__floats2half2_rn(acc[s][j][0], acc[s][j][1]));
                __half2 e23 = h2exp2(__floats2half2_rn(acc[s][j][2], acc[s][j][3]));
                rs01[s] = __hadd2(rs01[s], e01);
                rs23[s] = __hadd2(rs23[s], e23);
                csm[j]  = __hadd2(csm[j], __hadd2(e01, e23));
            }
#pragma unroll
        for (int s = 0; s < 4; s++) {
            rp[s * 2]     = __low2float(rs01[s]) + __high2float(rs01[s]);
            rp[s * 2 + 1] = __low2float(rs23[s]) + __high2float(rs23[s]);
        }
#pragma unroll
        for (int j = 0; j < 4; j++) {
            cp[j * 2]     = __low2float(csm[j]);
            cp[j * 2 + 1] = __high2float(csm[j]);
        }
    } else {
        const int rbase = r0 + wm * 64;
        const int cbase = c0 + wn * 32;
#pragma unroll
        for (int i = 0; i < 8; i++) { rp[i] = 0.0f; cp[i] = 0.0f; }
#pragma unroll
        for (int s = 0; s < 4; s++)
#pragma unroll
            for (int j = 0; j < 4; j++)
#pragma unroll
                for (int g = 0; g < 4; g++) {
                    int R = rbase + s * 16 + rl + ((g >> 1) << 3);
                    int C = cbase + j * 8 + cl2 + (g & 1);
                    float e = ex2f(acc[s][j][g]);
                    if (R == C) e = 0.0f;
                    rp[s * 2 + (g >> 1)] += e;
                    cp[j * 2 + (g & 1)]  += e;
                }
    }

#pragma unroll
    for (int i = 0; i < 8; i++) {
        rp[i] += __shfl_xor_sync(0xFFFFFFFFu, rp[i], 1);
        rp[i] += __shfl_xor_sync(0xFFFFFFFFu, rp[i], 2);
    }
#pragma unroll
    for (int i = 0; i < 8; i++) {
        cp[i] += __shfl_xor_sync(0xFFFFFFFFu, cp[i], 4);
        cp[i] += __shfl_xor_sync(0xFFFFFFFFu, cp[i], 8);
        cp[i] += __shfl_xor_sync(0xFFFFFFFFu, cp[i], 16);
    }

    float* rowred = reinterpret_cast<float*>(smem);      // [4][128]
    float* colred = rowred + 512;                        // [2][128]
    __syncthreads();   // all warps out of mainloop before smem reuse
    if ((lane & 3) == 0) {
#pragma unroll
        for (int s = 0; s < 4; s++)
#pragma unroll
            for (int h = 0; h < 2; h++)
                rowred[wn * 128 + wm * 64 + s * 16 + h * 8 + rl] = rp[s * 2 + h];
    }
    if (lane < 4) {
#pragma unroll
        for (int j = 0; j < 4; j++)
#pragma unroll
            for (int b = 0; b < 2; b++)
                colred[wm * 128 + wn * 32 + j * 8 + cl2 + b] = cp[j * 2 + b];
    }
    __syncthreads();

    if (tid < 128) {
        float rs = rowred[tid] + rowred[128 + tid] + rowred[256 + tid] + rowred[384 + tid];
        atomicAdd(&g_rowsum[loss * NN + r0 + tid], rs);
        if (!diag) {
            float cs = colred[tid] + colred[128 + tid];
            atomicAdd(&g_rowsum[loss * NN + c0 + tid], cs);
        }
    }
}

// ---------------------------------------------------------------------------
// 3) ortho losses: mean(1 - cos) from scaled bf16 rows. One warp per (pair,row).
// ---------------------------------------------------------------------------
__global__ void ortho_kernel(float* out) {
    int gw   = (blockIdx.x * blockDim.x + threadIdx.x) >> 5;
    int lane = threadIdx.x & 31;
    __shared__ float red[8];
    float c = 0.0f;
    if (gw < NORTHO * BB) {
        int p = gw / BB;
        int r = gw % BB;
        const __nv_bfloat16* a = g_zhi + (size_t)c_opA[p] * BB * DD + (size_t)r * DD;
        const __nv_bfloat16* b = g_zhi + (size_t)c_opB[p] * BB * DD + (size_t)r * DD;
        float d = bf16_row_dot(a, b, lane);        // = cos * SCALE_K2
        if (lane == 0) c = (1.0f - d * (1.0f / SCALE_K2)) * (1.0f / (float)BB);
    }
#pragma unroll
    for (int o = 16; o; o >>= 1) c += __shfl_xor_sync(0xFFFFFFFFu, c, o);
    if (lane == 0) red[threadIdx.x >> 5] = c;
    __syncthreads();
    if (threadIdx.x < 8) {
        float v = red[threadIdx.x];
#pragma unroll
        for (int o = 4; o; o >>= 1) v += __shfl_xor_sync(0xFFu, v, o);
        if (threadIdx.x == 0) atomicAdd(out, v);
    }
}

// ---------------------------------------------------------------------------
// 4) finalize contrastive: log(rowsum) minus pos dot (scaled bf16).
// ---------------------------------------------------------------------------
__global__ void finalize_kernel(float* out) {
    int gw   = (blockIdx.x * blockDim.x + threadIdx.x) >> 5;
    int lane = threadIdx.x & 31;
    __shared__ float red[8];
    float c = 0.0f;
    if (gw < NLOSS * NN) {
        int loss = gw / NN;
        int i    = gw % NN;
        float val = logf(g_rowsum[loss * NN + i]);
        if (i < BB) {
            const __nv_bfloat16* a = g_zhi + (size_t)c_cpA[loss] * BB * DD + (size_t)i * DD;
            const __nv_bfloat16* b = g_zhi + (size_t)c_cpB[loss] * BB * DD + (size_t)i * DD;
            float d = bf16_row_dot(a, b, lane);    // = cos * TINV * log2(e)
            val -= 2.0f * d * LN2;                 // = 2 * cos * TINV (both rows)
        }
        if (lane == 0) c = val * (1.0f / (float)NN);
    }
#pragma unroll
    for (int o = 16; o; o >>= 1) c += __shfl_xor_sync(0xFFFFFFFFu, c, o);
    if (lane == 0) red[threadIdx.x >> 5] = c;
    __syncthreads();
    if (threadIdx.x < 8) {
        float v = red[threadIdx.x];
#pragma unroll
        for (int o = 4; o; o >>= 1) v += __shfl_xor_sync(0xFFu, v, o);
        if (threadIdx.x == 0) atomicAdd(out, v);
    }
}

// ---------------------------------------------------------------------------
extern "C" void kernel_launch(void* const* d_in, const int* in_sizes, int n_in,
                              void* d_out, int out_size) {
    (void)in_sizes; (void)n_in; (void)out_size;
    float* out = (float*)d_out;

    cudaFuncSetAttribute(ctile_kernel, cudaFuncAttributeMaxDynamicSharedMemorySize,
                         NSTG * STAGE);

    zero_kernel<<<(NLOSS * NN + 255) / 256, 256>>>(out);

    norm_kernel<<<(NHALF * BB) / 8, 256>>>(
        (const float*)d_in[0], (const float*)d_in[1], (const float*)d_in[2],
        (const float*)d_in[3], (const float*)d_in[4], (const float*)d_in[5]);

    dim3 grid(528, NLOSS);
    ctile_kernel<<<grid, 256, NSTG * STAGE>>>();

    ortho_kernel<<<(NORTHO * BB) / 8, 256>>>(out);
    finalize_kernel<<<(NLOSS * NN) / 8, 256>>>(out);
}

// round 10
// speedup vs baseline: 1.1237x; 1.1237x over previous
#include <cuda_runtime.h>
#include <cuda_bf16.h>
#include <cuda_fp16.h>
#include <math.h>
#include <stdint.h>

// Problem constants
#define BB 2048          // batch
#define NN 4096          // 2*B rows of z
#define DD 512           // half feature dim
#define NHALF 12         // 6 inputs x 2 halves
#define NLOSS 9          // contrastive losses
#define NORTHO 12        // ortho pairs
#define TINV 5.0f        // 1/temperature
// sqrt(TINV * log2(e)) folded into bf16 operands => acc = sim*TINV*log2e
#define SCALE_K  2.6857913787767947f
#define SCALE_K2 7.2134752044448170f   // TINV*log2(e)
#define LN2      0.6931471805599453f

// Scratch (device globals; no allocation allowed)
__device__ __nv_bfloat16 g_zhi[NHALF * BB * DD];   // bf16 normalized * SCALE_K
__device__ float         g_rowsum[NLOSS * NN];     // per-row sum of exp(sim/T)

__constant__ int c_cpA[NLOSS] = {0, 0, 2, 6, 6,  8, 1, 3, 5};
__constant__ int c_cpB[NLOSS] = {2, 4, 4, 8, 10, 10, 7, 9, 11};
__constant__ int c_opA[NORTHO] = {0, 2, 4, 1, 1, 3, 6, 8, 10, 7, 7, 9};
__constant__ int c_opB[NORTHO] = {1, 3, 5, 3, 5, 5, 7, 9, 11, 9, 11, 11};

// ---------------------------------------------------------------------------
__device__ __forceinline__ uint32_t smem_u32(const void* p) {
    uint32_t a;
    asm("{ .reg .u64 t; cvta.to.shared.u64 t, %1; cvt.u32.u64 %0, t; }" : "=r"(a) : "l"(p));
    return a;
}
__device__ __forceinline__ void cpasync16(uint32_t dst, const void* src) {
    asm volatile("cp.async.cg.shared.global [%0], [%1], 16;" :: "r"(dst), "l"(src));
}
__device__ __forceinline__ void ldsm4(uint32_t* r, uint32_t addr) {
    asm volatile("ldmatrix.sync.aligned.m8n8.x4.shared.b16 {%0,%1,%2,%3}, [%4];"
                 : "=r"(r[0]), "=r"(r[1]), "=r"(r[2]), "=r"(r[3]) : "r"(addr));
}
__device__ __forceinline__ void mma16816(float* d, const uint32_t* a,
                                         uint32_t b0, uint32_t b1) {
    asm volatile(
        "mma.sync.aligned.m16n8k16.row.col.f32.bf16.bf16.f32 "
        "{%0,%1,%2,%3}, {%4,%5,%6,%7}, {%8,%9}, {%0,%1,%2,%3};"
        : "+f"(d[0]), "+f"(d[1]), "+f"(d[2]), "+f"(d[3])
        : "r"(a[0]), "r"(a[1]), "r"(a[2]), "r"(a[3]), "r"(b0), "r"(b1));
}
__device__ __forceinline__ float ex2f(float x) {
    float r;
    asm("ex2.approx.f32 %0, %1;" : "=f"(r) : "f"(x));
    return r;
}
// bf16 row dot product (16 elems/lane, warp-reduced). Returns scaled dot.
__device__ __forceinline__ float bf16_row_dot(const __nv_bfloat16* a,
                                              const __nv_bfloat16* b, int lane) {
    uint4 xa = reinterpret_cast<const uint4*>(a)[lane];
    uint4 xb = reinterpret_cast<const uint4*>(b)[lane];
    const __nv_bfloat162* pa = reinterpret_cast<const __nv_bfloat162*>(&xa);
    const __nv_bfloat162* pb = reinterpret_cast<const __nv_bfloat162*>(&xb);
    float d = 0.0f;
#pragma unroll
    for (int i = 0; i < 8; i++) {
        float2 fa = __bfloat1622float2(pa[i]);
        float2 fb = __bfloat1622float2(pb[i]);
        d += fa.x * fb.x + fa.y * fb.y;
    }
#pragma unroll
    for (int o = 16; o; o >>= 1) d += __shfl_xor_sync(0xFFFFFFFFu, d, o);
    return d;
}

// ---------------------------------------------------------------------------
// 1) row-normalize all 12 halves -> scaled bf16; also zero rowsum + out.
//    One warp per row; zeroing folded in.
// ---------------------------------------------------------------------------
__global__ void norm_kernel(const float* __restrict__ i0, const float* __restrict__ i1,
                            const float* __restrict__ i2, const float* __restrict__ i3,
                            const float* __restrict__ i4, const float* __restrict__ i5,
                            float* out) {
    // fused zeroing (ordering vs ctile via kernel launch sequence)
    int gidx = blockIdx.x * blockDim.x + threadIdx.x;
    if (gidx < NLOSS * NN) g_rowsum[gidx] = 0.0f;
    if (gidx == 0) out[0] = 0.0f;

    int gw   = gidx >> 5;
    int lane = threadIdx.x & 31;
    if (gw >= NHALF * BB) return;
    int h = gw / BB;
    int r = gw % BB;
    int m = h >> 1;
    const float* base = (m == 0) ? i0 : (m == 1) ? i1 : (m == 2) ? i2
                       : (m == 3) ? i3 : (m == 4) ? i4 : i5;
    const float* src = base + (size_t)r * 1024 + (size_t)(h & 1) * 512;

    float4 v[4];
    float ss = 0.0f;
#pragma unroll
    for (int w = 0; w < 4; w++) {
        v[w] = reinterpret_cast<const float4*>(src)[lane + w * 32];
        ss += v[w].x * v[w].x + v[w].y * v[w].y + v[w].z * v[w].z + v[w].w * v[w].w;
    }
#pragma unroll
    for (int o = 16; o; o >>= 1) ss += __shfl_xor_sync(0xFFFFFFFFu, ss, o);
    float invk = SCALE_K / fmaxf(sqrtf(ss), 1e-8f);

    __nv_bfloat162* dhi = reinterpret_cast<__nv_bfloat162*>(
        g_zhi + (size_t)h * BB * DD + (size_t)r * DD);
#pragma unroll
    for (int w = 0; w < 4; w++) {
        int pi = (lane + w * 32) * 2;
        dhi[pi]     = __floats2bfloat162_rn(v[w].x * invk, v[w].y * invk);
        dhi[pi + 1] = __floats2bfloat162_rn(v[w].z * invk, v[w].w * invk);
    }
}

// ---------------------------------------------------------------------------
// 2) bf16 HMMA tile kernel: 128x128 sim tile, ex2 epilogue (acc pre-scaled).
//    Grid: x = 528 upper-triangle tiles, y = loss. 256 threads, 8 warps.
//    Warp tile 64x32. 3-stage cp.async pipeline (96KB smem), occ 2,
//    ONE __syncthreads per K-chunk.  (R6 champion mainloop, unchanged.)
// ---------------------------------------------------------------------------
#define KCHUNK 64
#define BUFSZ  16384          // 128 rows * 128 bytes
#define STAGE  32768          // A + B buffer per stage
#define NSTG   3
#define SWZOFF(row, seg) ((uint32_t)((row) * 128 + (((seg) ^ ((row) & 7)) << 4)))

__global__ __launch_bounds__(256, 2) void ctile_kernel() {
    extern __shared__ unsigned char smem[];
    const int loss = blockIdx.y;
    int t = blockIdx.x;
    int bi = 0;
    while (t >= 32 - bi) { t -= 32 - bi; bi++; }
    const int bj = bi + t;
    const int r0 = bi * 128, c0 = bj * 128;
    const bool diag = (bi == bj);
    const int tid = threadIdx.x, wid = tid >> 5, lane = tid & 31;
    const int wm = wid & 1, wn = wid >> 1;

    const __nv_bfloat16* ZA = g_zhi + (size_t)c_cpA[loss] * BB * DD;
    const __nv_bfloat16* ZB = g_zhi + (size_t)c_cpB[loss] * BB * DD;
    const __nv_bfloat16* sA = (r0 < BB) ? ZA + (size_t)r0 * DD : ZB + (size_t)(r0 - BB) * DD;
    const __nv_bfloat16* sB = (c0 < BB) ? ZA + (size_t)c0 * DD : ZB + (size_t)(c0 - BB) * DD;

    const uint32_t sbase = smem_u32(smem);

    float acc[4][4][4];
#pragma unroll
    for (int s = 0; s < 4; s++)
#pragma unroll
        for (int j = 0; j < 4; j++)
#pragma unroll
            for (int g = 0; g < 4; g++) acc[s][j][g] = 0.0f;

    // ---- prologue: prefetch chunks 0 and 1 into stages 0,1 ----
#pragma unroll
    for (int pc = 0; pc < 2; pc++) {
        const int kc = pc * KCHUNK;
        const uint32_t dbuf = sbase + pc * STAGE;
#pragma unroll
        for (int q = tid; q < 1024; q += 256) {
            int row = q >> 3, seg = q & 7;
            uint32_t off = SWZOFF(row, seg);
            cpasync16(dbuf + off,         sA + (size_t)row * DD + kc + seg * 8);
            cpasync16(dbuf + BUFSZ + off, sB + (size_t)row * DD + kc + seg * 8);
        }
        asm volatile("cp.async.commit_group;" ::: "memory");
    }

    uint32_t stg = 0;   // stage index of chunk c
    for (int c = 0; c < 8; c++) {
        if (c < 7) {
            asm volatile("cp.async.wait_group 1;" ::: "memory");
        } else {
            asm volatile("cp.async.wait_group 0;" ::: "memory");
        }
        __syncthreads();   // stage c visible to all; reads of stage c-1 done

        if (c < 6) {
            const int kc = (c + 2) * KCHUNK;
            uint32_t ds = stg + 2; if (ds >= NSTG) ds -= NSTG;
            const uint32_t dbuf = sbase + ds * STAGE;
#pragma unroll
            for (int q = tid; q < 1024; q += 256) {
                int row = q >> 3, seg = q & 7;
                uint32_t off = SWZOFF(row, seg);
                cpasync16(dbuf + off,         sA + (size_t)row * DD + kc + seg * 8);
                cpasync16(dbuf + BUFSZ + off, sB + (size_t)row * DD + kc + seg * 8);
            }
            asm volatile("cp.async.commit_group;" ::: "memory");
        }

        const uint32_t ab = sbase + stg * STAGE;
        const uint32_t bb = ab + BUFSZ;
#pragma unroll
        for (int kb = 0; kb < 4; kb++) {
            uint32_t af[4][4], bf[2][4];
#pragma unroll
            for (int s = 0; s < 4; s++) {
                int row = wm * 64 + s * 16 + (lane & 15);
                int seg = kb * 2 + (lane >> 4);
                ldsm4(af[s], ab + SWZOFF(row, seg));
            }
#pragma unroll
            for (int p = 0; p < 2; p++) {
                int row = wn * 32 + p * 16 + (lane & 7) + ((lane >> 4) << 3);
                int seg = kb * 2 + ((lane >> 3) & 1);
                ldsm4(bf[p], bb + SWZOFF(row, seg));
            }
#pragma unroll
            for (int s = 0; s < 4; s++)
#pragma unroll
                for (int j = 0; j < 4; j++)
                    mma16816(acc[s][j], af[s], bf[j >> 1][(j & 1) * 2],
                             bf[j >> 1][(j & 1) * 2 + 1]);
        }
        if (++stg >= NSTG) stg = 0;
    }

    // --------------------------- epilogue ---------------------------
    // acc == sim * TINV * log2(e); exp(sim/T) = ex2(acc)
    const int rl  = lane >> 2;          // row within 8-group
    const int cl2 = (lane & 3) * 2;     // col pair base

    float rp[8], cp[8];

    if (!diag) {
        __half2 rs01[4], rs23[4], csm[4];
#pragma unroll
        for (int i = 0; i < 4; i++) {
            rs01[i] = __float2half2_rn(0.0f);
            rs23[i] = __float2half2_rn(0.0f);
            csm[i]  = __float2half2_rn(0.0f);
        }
#pragma unroll
        for (int s = 0; s < 4; s++)
#pragma unroll
            for (int j = 0; j < 4; j++) {
                __half2 e01 = h2exp2(__floats2half2_rn(acc[s][j][0], acc[s][j][1]));
                __half2 e23 = h2exp2(__floats2half2_rn(acc[s][j][2], acc[s][j][3]));
                rs01[s] = __hadd2(rs01[s], e01);
                rs23[s] = __hadd2(rs23[s], e23);
                csm[j]  = __hadd2(csm[j], __hadd2(e01, e23));
            }
#pragma unroll
        for (int s = 0; s < 4; s++) {
            rp[s * 2]     = __low2float(rs01[s]) + __high2float(rs01[s]);
            rp[s * 2 + 1] = __low2float(rs23[s]) + __high2float(rs23[s]);
        }
#pragma unroll
        for (int j = 0; j < 4; j++) {
            cp[j * 2]     = __low2float(csm[j]);
            cp[j * 2 + 1] = __high2float(csm[j]);
        }
    } else {
        const int rbase = r0 + wm * 64;
        const int cbase = c0 + wn * 32;
#pragma unroll
        for (int i = 0; i < 8; i++) { rp[i] = 0.0f; cp[i] = 0.0f; }
#pragma unroll
        for (int s = 0; s < 4; s++)
#pragma unroll
            for (int j = 0; j < 4; j++)
#pragma unroll
                for (int g = 0; g < 4; g++) {
                    int R = rbase + s * 16 + rl + ((g >> 1) << 3);
                    int C = cbase + j * 8 + cl2 + (g & 1);
                    float e = ex2f(acc[s][j][g]);
                    if (R == C) e = 0.0f;
                    rp[s * 2 + (g >> 1)] += e;
                    cp[j * 2 + (g & 1)]  += e;
                }
    }

#pragma unroll
    for (int i = 0; i < 8; i++) {
        rp[i] += __shfl_xor_sync(0xFFFFFFFFu, rp[i], 1);
        rp[i] += __shfl_xor_sync(0xFFFFFFFFu, rp[i], 2);
    }
#pragma unroll
    for (int i = 0; i < 8; i++) {
        cp[i] += __shfl_xor_sync(0xFFFFFFFFu, cp[i], 4);
        cp[i] += __shfl_xor_sync(0xFFFFFFFFu, cp[i], 8);
        cp[i] += __shfl_xor_sync(0xFFFFFFFFu, cp[i], 16);
    }

    // reduction buffers reuse stage-0 smem (no longer read: holds chunk 6)
    float* rowred = reinterpret_cast<float*>(smem);      // [4][128]
    float* colred = rowred + 512;                        // [2][128]
    __syncthreads();   // all warps out of mainloop before reuse
    if ((lane & 3) == 0) {
#pragma unroll
        for (int s = 0; s < 4; s++)
#pragma unroll
            for (int h = 0; h < 2; h++)
                rowred[wn * 128 + wm * 64 + s * 16 + h * 8 + rl] = rp[s * 2 + h];
    }
    if (lane < 4) {
#pragma unroll
        for (int j = 0; j < 4; j++)
#pragma unroll
            for (int b = 0; b < 2; b++)
                colred[wm * 128 + wn * 32 + j * 8 + cl2 + b] = cp[j * 2 + b];
    }
    __syncthreads();

    if (tid < 128) {
        float rs = rowred[tid] + rowred[128 + tid] + rowred[256 + tid] + rowred[384 + tid];
        atomicAdd(&g_rowsum[loss * NN + r0 + tid], rs);
        if (!diag) {
            float cs = colred[tid] + colred[128 + tid];
            atomicAdd(&g_rowsum[loss * NN + c0 + tid], cs);
        }
    }
}

// ---------------------------------------------------------------------------
// 3) tail kernel: fused ortho losses + contrastive finalize.
//    One warp per work item; first NORTHO*BB warps do ortho, rest finalize.
// ---------------------------------------------------------------------------
#define ORTHO_W  (NORTHO * BB)          // 24576 ortho warp-items
#define FINAL_W  (NLOSS * NN)           // 36864 finalize warp-items
#define TAIL_W   (ORTHO_W + FINAL_W)    // 61440 total

__global__ void tail_kernel(float* out) {
    int gw   = (blockIdx.x * blockDim.x + threadIdx.x) >> 5;
    int lane = threadIdx.x & 31;
    __shared__ float red[8];
    float c = 0.0f;
    if (gw < ORTHO_W) {
        int p = gw / BB;
        int r = gw % BB;
        const __nv_bfloat16* a = g_zhi + (size_t)c_opA[p] * BB * DD + (size_t)r * DD;
        const __nv_bfloat16* b = g_zhi + (size_t)c_opB[p] * BB * DD + (size_t)r * DD;
        float d = bf16_row_dot(a, b, lane);        // = cos * SCALE_K2
        if (lane == 0) c = (1.0f - d * (1.0f / SCALE_K2)) * (1.0f / (float)BB);
    } else if (gw < TAIL_W) {
        int q    = gw - ORTHO_W;
        int loss = q / NN;
        int i    = q % NN;
        float val = logf(g_rowsum[loss * NN + i]);
        if (i < BB) {
            const __nv_bfloat16* a = g_zhi + (size_t)c_cpA[loss] * BB * DD + (size_t)i * DD;
            const __nv_bfloat16* b = g_zhi + (size_t)c_cpB[loss] * BB * DD + (size_t)i * DD;
            float d = bf16_row_dot(a, b, lane);    // = cos * TINV * log2(e)
            val -= 2.0f * d * LN2;                 // = 2 * cos * TINV (both rows)
        }
        if (lane == 0) c = val * (1.0f / (float)NN);
    }
#pragma unroll
    for (int o = 16; o; o >>= 1) c += __shfl_xor_sync(0xFFFFFFFFu, c, o);
    if (lane == 0) red[threadIdx.x >> 5] = c;
    __syncthreads();
    if (threadIdx.x < 8) {
        float v = red[threadIdx.x];
#pragma unroll
        for (int o = 4; o; o >>= 1) v += __shfl_xor_sync(0xFFu, v, o);
        if (threadIdx.x == 0) atomicAdd(out, v);
    }
}

// ---------------------------------------------------------------------------
extern "C" void kernel_launch(void* const* d_in, const int* in_sizes, int n_in,
                              void* d_out, int out_size) {
    (void)in_sizes; (void)n_in; (void)out_size;
    float* out = (float*)d_out;

    cudaFuncSetAttribute(ctile_kernel, cudaFuncAttributeMaxDynamicSharedMemorySize,
                         NSTG * STAGE);

    norm_kernel<<<(NHALF * BB) / 8, 256>>>(
        (const float*)d_in[0], (const float*)d_in[1], (const float*)d_in[2],
        (const float*)d_in[3], (const float*)d_in[4], (const float*)d_in[5], out);

    dim3 grid(528, NLOSS);
    ctile_kernel<<<grid, 256, NSTG * STAGE>>>();

    tail_kernel<<<TAIL_W / 8, 256>>>(out);
}

// round 11
// speedup vs baseline: 1.1517x; 1.0249x over previous
#include <cuda_runtime.h>
#include <cuda_bf16.h>
#include <cuda_fp16.h>
#include <math.h>
#include <stdint.h>

// Problem constants
#define BB 2048          // batch
#define NN 4096          // 2*B rows of z
#define DD 512           // half feature dim
#define NHALF 12         // 6 inputs x 2 halves
#define NLOSS 9          // contrastive losses
#define NORTHO 12        // ortho pairs
#define TINV 5.0f        // 1/temperature
// sqrt(TINV * log2(e)) folded into bf16 operands => acc = sim*TINV*log2e
#define SCALE_K  2.6857913787767947f
#define SCALE_K2 7.2134752044448170f   // TINV*log2(e)
#define LN2      0.6931471805599453f

// Scratch (device globals; no allocation allowed)
__device__ __nv_bfloat16 g_zhi[NHALF * BB * DD];   // bf16 normalized * SCALE_K
__device__ float         g_rowsum[NLOSS * NN];     // per-row sum of exp(sim/T)
__device__ float         g_pos[NLOSS * BB];        // pos sim * TINV*log2e (from ctile)

__constant__ int c_cpA[NLOSS] = {0, 0, 2, 6, 6,  8, 1, 3, 5};
__constant__ int c_cpB[NLOSS] = {2, 4, 4, 8, 10, 10, 7, 9, 11};
__constant__ int c_opA[NORTHO] = {0, 2, 4, 1, 1, 3, 6, 8, 10, 7, 7, 9};
__constant__ int c_opB[NORTHO] = {1, 3, 5, 3, 5, 5, 7, 9, 11, 9, 11, 11};

// ---------------------------------------------------------------------------
__device__ __forceinline__ uint32_t smem_u32(const void* p) {
    uint32_t a;
    asm("{ .reg .u64 t; cvta.to.shared.u64 t, %1; cvt.u32.u64 %0, t; }" : "=r"(a) : "l"(p));
    return a;
}
__device__ __forceinline__ void cpasync16(uint32_t dst, const void* src) {
    asm volatile("cp.async.cg.shared.global [%0], [%1], 16;" :: "r"(dst), "l"(src));
}
__device__ __forceinline__ void ldsm4(uint32_t* r, uint32_t addr) {
    asm volatile("ldmatrix.sync.aligned.m8n8.x4.shared.b16 {%0,%1,%2,%3}, [%4];"
                 : "=r"(r[0]), "=r"(r[1]), "=r"(r[2]), "=r"(r[3]) : "r"(addr));
}
__device__ __forceinline__ void mma16816(float* d, const uint32_t* a,
                                         uint32_t b0, uint32_t b1) {
    asm volatile(
        "mma.sync.aligned.m16n8k16.row.col.f32.bf16.bf16.f32 "
        "{%0,%1,%2,%3}, {%4,%5,%6,%7}, {%8,%9}, {%0,%1,%2,%3};"
        : "+f"(d[0]), "+f"(d[1]), "+f"(d[2]), "+f"(d[3])
        : "r"(a[0]), "r"(a[1]), "r"(a[2]), "r"(a[3]), "r"(b0), "r"(b1));
}
__device__ __forceinline__ float ex2f(float x) {
    float r;
    asm("ex2.approx.f32 %0, %1;" : "=f"(r) : "f"(x));
    return r;
}
// bf16 row dot product: full 512 elems (2 x uint4 per lane), warp-reduced.
__device__ __forceinline__ float bf16_row_dot(const __nv_bfloat16* a,
                                              const __nv_bfloat16* b, int lane) {
    float d = 0.0f;
#pragma unroll
    for (int w = 0; w < 2; w++) {
        uint4 xa = reinterpret_cast<const uint4*>(a)[lane + w * 32];
        uint4 xb = reinterpret_cast<const uint4*>(b)[lane + w * 32];
        const __nv_bfloat162* pa = reinterpret_cast<const __nv_bfloat162*>(&xa);
        const __nv_bfloat162* pb = reinterpret_cast<const __nv_bfloat162*>(&xb);
#pragma unroll
        for (int i = 0; i < 4; i++) {
            float2 fa = __bfloat1622float2(pa[i]);
            float2 fb = __bfloat1622float2(pb[i]);
            d += fa.x * fb.x + fa.y * fb.y;
        }
    }
#pragma unroll
    for (int o = 16; o; o >>= 1) d += __shfl_xor_sync(0xFFFFFFFFu, d, o);
    return d;
}

// ---------------------------------------------------------------------------
// 1) row-normalize all 12 halves -> scaled bf16; also zero rowsum + out.
// ---------------------------------------------------------------------------
__global__ void norm_kernel(const float* __restrict__ i0, const float* __restrict__ i1,
                            const float* __restrict__ i2, const float* __restrict__ i3,
                            const float* __restrict__ i4, const float* __restrict__ i5,
                            float* out) {
    int gidx = blockIdx.x * blockDim.x + threadIdx.x;
    if (gidx < NLOSS * NN) g_rowsum[gidx] = 0.0f;
    if (gidx == 0) out[0] = 0.0f;

    int gw   = gidx >> 5;
    int lane = threadIdx.x & 31;
    if (gw >= NHALF * BB) return;
    int h = gw / BB;
    int r = gw % BB;
    int m = h >> 1;
    const float* base = (m == 0) ? i0 : (m == 1) ? i1 : (m == 2) ? i2
                       : (m == 3) ? i3 : (m == 4) ? i4 : i5;
    const float* src = base + (size_t)r * 1024 + (size_t)(h & 1) * 512;

    float4 v[4];
    float ss = 0.0f;
#pragma unroll
    for (int w = 0; w < 4; w++) {
        v[w] = reinterpret_cast<const float4*>(src)[lane + w * 32];
        ss += v[w].x * v[w].x + v[w].y * v[w].y + v[w].z * v[w].z + v[w].w * v[w].w;
    }
#pragma unroll
    for (int o = 16; o; o >>= 1) ss += __shfl_xor_sync(0xFFFFFFFFu, ss, o);
    float invk = SCALE_K / fmaxf(sqrtf(ss), 1e-8f);

    __nv_bfloat162* dhi = reinterpret_cast<__nv_bfloat162*>(
        g_zhi + (size_t)h * BB * DD + (size_t)r * DD);
#pragma unroll
    for (int w = 0; w < 4; w++) {
        int pi = (lane + w * 32) * 2;
        dhi[pi]     = __floats2bfloat162_rn(v[w].x * invk, v[w].y * invk);
        dhi[pi + 1] = __floats2bfloat162_rn(v[w].z * invk, v[w].w * invk);
    }
}

// ---------------------------------------------------------------------------
// 2) bf16 HMMA tile kernel: 128x128 sim tile, ex2 epilogue (acc pre-scaled).
//    R6 champion mainloop; adds pos capture on tiles with c0 == r0 + BB.
// ---------------------------------------------------------------------------
#define KCHUNK 64
#define BUFSZ  16384          // 128 rows * 128 bytes
#define STAGE  32768          // A + B buffer per stage
#define NSTG   3
#define SWZOFF(row, seg) ((uint32_t)((row) * 128 + (((seg) ^ ((row) & 7)) << 4)))

__global__ __launch_bounds__(256, 2) void ctile_kernel() {
    extern __shared__ unsigned char smem[];
    const int loss = blockIdx.y;
    int t = blockIdx.x;
    int bi = 0;
    while (t >= 32 - bi) { t -= 32 - bi; bi++; }
    const int bj = bi + t;
    const int r0 = bi * 128, c0 = bj * 128;
    const bool diag = (bi == bj);
    const int tid = threadIdx.x, wid = tid >> 5, lane = tid & 31;
    const int wm = wid & 1, wn = wid >> 1;

    const __nv_bfloat16* ZA = g_zhi + (size_t)c_cpA[loss] * BB * DD;
    const __nv_bfloat16* ZB = g_zhi + (size_t)c_cpB[loss] * BB * DD;
    const __nv_bfloat16* sA = (r0 < BB) ? ZA + (size_t)r0 * DD : ZB + (size_t)(r0 - BB) * DD;
    const __nv_bfloat16* sB = (c0 < BB) ? ZA + (size_t)c0 * DD : ZB + (size_t)(c0 - BB) * DD;

    const uint32_t sbase = smem_u32(smem);

    float acc[4][4][4];
#pragma unroll
    for (int s = 0; s < 4; s++)
#pragma unroll
        for (int j = 0; j < 4; j++)
#pragma unroll
            for (int g = 0; g < 4; g++) acc[s][j][g] = 0.0f;

    // ---- prologue: prefetch chunks 0 and 1 into stages 0,1 ----
#pragma unroll
    for (int pc = 0; pc < 2; pc++) {
        const int kc = pc * KCHUNK;
        const uint32_t dbuf = sbase + pc * STAGE;
#pragma unroll
        for (int q = tid; q < 1024; q += 256) {
            int row = q >> 3, seg = q & 7;
            uint32_t off = SWZOFF(row, seg);
            cpasync16(dbuf + off,         sA + (size_t)row * DD + kc + seg * 8);
            cpasync16(dbuf + BUFSZ + off, sB + (size_t)row * DD + kc + seg * 8);
        }
        asm volatile("cp.async.commit_group;" ::: "memory");
    }

    uint32_t stg = 0;   // stage index of chunk c
    for (int c = 0; c < 8; c++) {
        if (c < 7) {
            asm volatile("cp.async.wait_group 1;" ::: "memory");
        } else {
            asm volatile("cp.async.wait_group 0;" ::: "memory");
        }
        __syncthreads();   // stage c visible to all; reads of stage c-1 done

        if (c < 6) {
            const int kc = (c + 2) * KCHUNK;
            uint32_t ds = stg + 2; if (ds >= NSTG) ds -= NSTG;
            const uint32_t dbuf = sbase + ds * STAGE;
#pragma unroll
            for (int q = tid; q < 1024; q += 256) {
                int row = q >> 3, seg = q & 7;
                uint32_t off = SWZOFF(row, seg);
                cpasync16(dbuf + off,         sA + (size_t)row * DD + kc + seg * 8);
                cpasync16(dbuf + BUFSZ + off, sB + (size_t)row * DD + kc + seg * 8);
            }
            asm volatile("cp.async.commit_group;" ::: "memory");
        }

        const uint32_t ab = sbase + stg * STAGE;
        const uint32_t bb = ab + BUFSZ;
#pragma unroll
        for (int kb = 0; kb < 4; kb++) {
            uint32_t af[4][4], bf[2][4];
#pragma unroll
            for (int s = 0; s < 4; s++) {
                int row = wm * 64 + s * 16 + (lane & 15);
                int seg = kb * 2 + (lane >> 4);
                ldsm4(af[s], ab + SWZOFF(row, seg));
            }
#pragma unroll
            for (int p = 0; p < 2; p++) {
                int row = wn * 32 + p * 16 + (lane & 7) + ((lane >> 4) << 3);
                int seg = kb * 2 + ((lane >> 3) & 1);
                ldsm4(bf[p], bb + SWZOFF(row, seg));
            }
#pragma unroll
            for (int s = 0; s < 4; s++)
#pragma unroll
                for (int j = 0; j < 4; j++)
                    mma16816(acc[s][j], af[s], bf[j >> 1][(j & 1) * 2],
                             bf[j >> 1][(j & 1) * 2 + 1]);
        }
        if (++stg >= NSTG) stg = 0;
    }

    // --------------------------- epilogue ---------------------------
    // acc == sim * TINV * log2(e); exp(sim/T) = ex2(acc)
    const int rl  = lane >> 2;          // row within 8-group
    const int cl2 = (lane & 3) * 2;     // col pair base

    // pos capture: tiles where column block = row block + BB hold the
    // positive-pair entries on their local diagonal (R_local == C_local).
    if (c0 == r0 + BB) {
#pragma unroll
        for (int s = 0; s < 4; s++)
#pragma unroll
            for (int j = 0; j < 4; j++)
#pragma unroll
                for (int g = 0; g < 4; g++) {
                    int R_ = wm * 64 + s * 16 + rl + ((g >> 1) << 3);
                    int C_ = wn * 32 + j * 8 + cl2 + (g & 1);
                    if (R_ == C_) g_pos[loss * BB + r0 + R_] = acc[s][j][g];
                }
    }

    float rp[8], cp[8];

    if (!diag) {
        __half2 rs01[4], rs23[4], csm[4];
#pragma unroll
        for (int i = 0; i < 4; i++) {
            rs01[i] = __float2half2_rn(0.0f);
            rs23[i] = __float2half2_rn(0.0f);
            csm[i]  = __float2half2_rn(0.0f);
        }
#pragma unroll
        for (int s = 0; s < 4; s++)
#pragma unroll
            for (int j = 0; j < 4; j++) {
                __half2 e01 = h2exp2(__floats2half2_rn(acc[s][j][0], acc[s][j][1]));
                __half2 e23 = h2exp2(__floats2half2_rn(acc[s][j][2], acc[s][j][3]));
                rs01[s] = __hadd2(rs01[s], e01);
                rs23[s] = __hadd2(rs23[s], e23);
                csm[j]  = __hadd2(csm[j], __hadd2(e01, e23));
            }
#pragma unroll
        for (int s = 0; s < 4; s++) {
            rp[s * 2]     = __low2float(rs01[s]) + __high2float(rs01[s]);
            rp[s * 2 + 1] = __low2float(rs23[s]) + __high2float(rs23[s]);
        }
#pragma unroll
        for (int j = 0; j < 4; j++) {
            cp[j * 2]     = __low2float(csm[j]);
            cp[j * 2 + 1] = __high2float(csm[j]);
        }
    } else {
        const int rbase = r0 + wm * 64;
        const int cbase = c0 + wn * 32;
#pragma unroll
        for (int i = 0; i < 8; i++) { rp[i] = 0.0f; cp[i] = 0.0f; }
#pragma unroll
        for (int s = 0; s < 4; s++)
#pragma unroll
            for (int j = 0; j < 4; j++)
#pragma unroll
                for (int g = 0; g < 4; g++) {
                    int R = rbase + s * 16 + rl + ((g >> 1) << 3);
                    int C = cbase + j * 8 + cl2 + (g & 1);
                    float e = ex2f(acc[s][j][g]);
                    if (R == C) e = 0.0f;
                    rp[s * 2 + (g >> 1)] += e;
                    cp[j * 2 + (g & 1)]  += e;
                }
    }

#pragma unroll
    for (int i = 0; i < 8; i++) {
        rp[i] += __shfl_xor_sync(0xFFFFFFFFu, rp[i], 1);
        rp[i] += __shfl_xor_sync(0xFFFFFFFFu, rp[i], 2);
    }
#pragma unroll
    for (int i = 0; i < 8; i++) {
        cp[i] += __shfl_xor_sync(0xFFFFFFFFu, cp[i], 4);
        cp[i] += __shfl_xor_sync(0xFFFFFFFFu, cp[i], 8);
        cp[i] += __shfl_xor_sync(0xFFFFFFFFu, cp[i], 16);
    }

    // reduction buffers reuse stage-0 smem (no longer read: holds chunk 6)
    float* rowred = reinterpret_cast<float*>(smem);      // [4][128]
    float* colred = rowred + 512;                        // [2][128]
    __syncthreads();   // all warps out of mainloop before reuse
    if ((lane & 3) == 0) {
#pragma unroll
        for (int s = 0; s < 4; s++)
#pragma unroll
            for (int h = 0; h < 2; h++)
                rowred[wn * 128 + wm * 64 + s * 16 + h * 8 + rl] = rp[s * 2 + h];
    }
    if (lane < 4) {
#pragma unroll
        for (int j = 0; j < 4; j++)
#pragma unroll
            for (int b = 0; b < 2; b++)
                colred[wm * 128 + wn * 32 + j * 8 + cl2 + b] = cp[j * 2 + b];
    }
    __syncthreads();

    if (tid < 128) {
        float rs = rowred[tid] + rowred[128 + tid] + rowred[256 + tid] + rowred[384 + tid];
        atomicAdd(&g_rowsum[loss * NN + r0 + tid], rs);
        if (!diag) {
            float cs = colred[tid] + colred[128 + tid];
            atomicAdd(&g_rowsum[loss * NN + c0 + tid], cs);
        }
    }
}

// ---------------------------------------------------------------------------
// 3) tail kernel: ortho dots (one warp/pair-row) + element-wise finalize
//    using pos values captured by ctile (no dot products needed).
// ---------------------------------------------------------------------------
#define ORTHO_W  (NORTHO * BB)              // 24576 ortho warp-items
#define FINW     (NLOSS * NN / 32)          // 1152 finalize warps (32 elems each)
#define TAIL_W   (ORTHO_W + FINW)           // 25728 total warps

__global__ void tail_kernel(float* out) {
    int gw   = (blockIdx.x * blockDim.x + threadIdx.x) >> 5;
    int lane = threadIdx.x & 31;
    __shared__ float red[8];
    float c = 0.0f;
    if (gw < ORTHO_W) {
        int p = gw / BB;
        int r = gw % BB;
        const __nv_bfloat16* a = g_zhi + (size_t)c_opA[p] * BB * DD + (size_t)r * DD;
        const __nv_bfloat16* b = g_zhi + (size_t)c_opB[p] * BB * DD + (size_t)r * DD;
        float d = bf16_row_dot(a, b, lane);        // = cos * SCALE_K2
        if (lane == 0) c = (1.0f - d * (1.0f / SCALE_K2)) * (1.0f / (float)BB);
    } else if (gw < TAIL_W) {
        int q    = (gw - ORTHO_W) * 32 + lane;     // 0 .. NLOSS*NN-1
        int loss = q >> 12;                        // /NN (NN=4096)
        int i    = q & (NN - 1);
        float val = logf(g_rowsum[q]);
        if (i < BB) val -= 2.0f * LN2 * g_pos[loss * BB + i];  // pos_i == pos_{i+B}
        c = val * (1.0f / (float)NN);
    }
#pragma unroll
    for (int o = 16; o; o >>= 1) c += __shfl_xor_sync(0xFFFFFFFFu, c, o);
    if (lane == 0) red[threadIdx.x >> 5] = c;
    __syncthreads();
    if (threadIdx.x < 8) {
        float v = red[threadIdx.x];
#pragma unroll
        for (int o = 4; o; o >>= 1) v += __shfl_xor_sync(0xFFu, v, o);
        if (threadIdx.x == 0) atomicAdd(out, v);
    }
}

// ---------------------------------------------------------------------------
extern "C" void kernel_launch(void* const* d_in, const int* in_sizes, int n_in,
                              void* d_out, int out_size) {
    (void)in_sizes; (void)n_in; (void)out_size;
    float* out = (float*)d_out;

    cudaFuncSetAttribute(ctile_kernel, cudaFuncAttributeMaxDynamicSharedMemorySize,
                         NSTG * STAGE);

    norm_kernel<<<(NHALF * BB) / 8, 256>>>(
        (const float*)d_in[0], (const float*)d_in[1], (const float*)d_in[2],
        (const float*)d_in[3], (const float*)d_in[4], (const float*)d_in[5], out);

    dim3 grid(528, NLOSS);
    ctile_kernel<<<grid, 256, NSTG * STAGE>>>();

    tail_kernel<<<TAIL_W / 8, 256>>>(out);
}

// round 13
// speedup vs baseline: 1.1848x; 1.0288x over previous
#include <cuda_runtime.h>
#include <cuda_bf16.h>
#include <cuda_fp16.h>
#include <math.h>
#include <stdint.h>

// Problem constants
#define BB 2048          // batch
#define NN 4096          // 2*B rows of z
#define DD 512           // half feature dim
#define NHALF 12         // 6 inputs x 2 halves
#define NLOSS 9          // contrastive losses
#define NORTHO 12        // ortho pairs
#define TINV 5.0f        // 1/temperature
// sqrt(TINV * log2(e)) folded into bf16 operands => acc = sim*TINV*log2e
#define SCALE_K  2.6857913787767947f
#define SCALE_K2 7.2134752044448170f   // TINV*log2(e)
#define LN2      0.6931471805599453f

// Scratch (device globals; no allocation allowed)
__device__ __nv_bfloat16 g_zhi[NHALF * BB * DD];   // bf16 normalized * SCALE_K
__device__ float         g_rowsum[NLOSS * NN];     // per-row sum of exp(sim/T)
__device__ float         g_pos[NLOSS * BB];        // pos sim * TINV*log2e (from ctile)

__constant__ int c_cpA[NLOSS] = {0, 0, 2, 6, 6,  8, 1, 3, 5};
__constant__ int c_cpB[NLOSS] = {2, 4, 4, 8, 10, 10, 7, 9, 11};
__constant__ int c_opA[NORTHO] = {0, 2, 4, 1, 1, 3, 6, 8, 10, 7, 7, 9};
__constant__ int c_opB[NORTHO] = {1, 3, 5, 3, 5, 5, 7, 9, 11, 9, 11, 11};

// ---------------------------------------------------------------------------
__device__ __forceinline__ uint32_t smem_u32(const void* p) {
    uint32_t a;
    asm("{ .reg .u64 t; cvta.to.shared.u64 t, %1; cvt.u32.u64 %0, t; }" : "=r"(a) : "l"(p));
    return a;
}
__device__ __forceinline__ void cpasync16(uint32_t dst, const void* src) {
    asm volatile("cp.async.cg.shared.global [%0], [%1], 16;" :: "r"(dst), "l"(src));
}
__device__ __forceinline__ void ldsm4(uint32_t* r, uint32_t addr) {
    asm volatile("ldmatrix.sync.aligned.m8n8.x4.shared.b16 {%0,%1,%2,%3}, [%4];"
                 : "=r"(r[0]), "=r"(r[1]), "=r"(r[2]), "=r"(r[3]) : "r"(addr));
}
__device__ __forceinline__ void mma16816(float* d, const uint32_t* a,
                                         uint32_t b0, uint32_t b1) {
    asm volatile(
        "mma.sync.aligned.m16n8k16.row.col.f32.bf16.bf16.f32 "
        "{%0,%1,%2,%3}, {%4,%5,%6,%7}, {%8,%9}, {%0,%1,%2,%3};"
        : "+f"(d[0]), "+f"(d[1]), "+f"(d[2]), "+f"(d[3])
        : "r"(a[0]), "r"(a[1]), "r"(a[2]), "r"(a[3]), "r"(b0), "r"(b1));
}
__device__ __forceinline__ float ex2f(float x) {
    float r;
    asm("ex2.approx.f32 %0, %1;" : "=f"(r) : "f"(x));
    return r;
}
// bf16 row dot product: full 512 elems (2 x uint4 per lane), warp-reduced.
__device__ __forceinline__ float bf16_row_dot(const __nv_bfloat16* a,
                                              const __nv_bfloat16* b, int lane) {
    float d = 0.0f;
#pragma unroll
    for (int w = 0; w < 2; w++) {
        uint4 xa = reinterpret_cast<const uint4*>(a)[lane + w * 32];
        uint4 xb = reinterpret_cast<const uint4*>(b)[lane + w * 32];
        const __nv_bfloat162* pa = reinterpret_cast<const __nv_bfloat162*>(&xa);
        const __nv_bfloat162* pb = reinterpret_cast<const __nv_bfloat162*>(&xb);
#pragma unroll
        for (int i = 0; i < 4; i++) {
            float2 fa = __bfloat1622float2(pa[i]);
            float2 fb = __bfloat1622float2(pb[i]);
            d += fa.x * fb.x + fa.y * fb.y;
        }
    }
#pragma unroll
    for (int o = 16; o; o >>= 1) d += __shfl_xor_sync(0xFFFFFFFFu, d, o);
    return d;
}

// ---------------------------------------------------------------------------
// 1) row-normalize all 12 halves -> scaled bf16; also zero rowsum + out.
// ---------------------------------------------------------------------------
__global__ void norm_kernel(const float* __restrict__ i0, const float* __restrict__ i1,
                            const float* __restrict__ i2, const float* __restrict__ i3,
                            const float* __restrict__ i4, const float* __restrict__ i5,
                            float* out) {
    int gidx = blockIdx.x * blockDim.x + threadIdx.x;
    if (gidx < NLOSS * NN) g_rowsum[gidx] = 0.0f;
    if (gidx == 0) out[0] = 0.0f;

    int gw   = gidx >> 5;
    int lane = threadIdx.x & 31;
    if (gw >= NHALF * BB) return;
    int h = gw / BB;
    int r = gw % BB;
    int m = h >> 1;
    const float* base = (m == 0) ? i0 : (m == 1) ? i1 : (m == 2) ? i2
                       : (m == 3) ? i3 : (m == 4) ? i4 : i5;
    const float* src = base + (size_t)r * 1024 + (size_t)(h & 1) * 512;

    float4 v[4];
    float ss = 0.0f;
#pragma unroll
    for (int w = 0; w < 4; w++) {
        v[w] = reinterpret_cast<const float4*>(src)[lane + w * 32];
        ss += v[w].x * v[w].x + v[w].y * v[w].y + v[w].z * v[w].z + v[w].w * v[w].w;
    }
#pragma unroll
    for (int o = 16; o; o >>= 1) ss += __shfl_xor_sync(0xFFFFFFFFu, ss, o);
    float invk = SCALE_K / fmaxf(sqrtf(ss), 1e-8f);

    __nv_bfloat162* dhi = reinterpret_cast<__nv_bfloat162*>(
        g_zhi + (size_t)h * BB * DD + (size_t)r * DD);
#pragma unroll
    for (int w = 0; w < 4; w++) {
        int pi = (lane + w * 32) * 2;
        dhi[pi]     = __floats2bfloat162_rn(v[w].x * invk, v[w].y * invk);
        dhi[pi + 1] = __floats2bfloat162_rn(v[w].z * invk, v[w].w * invk);
    }
}

// ---------------------------------------------------------------------------
// 2) bf16 HMMA tile kernel: 128x128 sim tile, ex2 epilogue (acc pre-scaled).
//    NEW: 4 warps (128 thr), 64x64 warp tiles (LDSM:MMA 8:32), occ 2,
//    3-stage cp.async pipeline, one __syncthreads per chunk.
// ---------------------------------------------------------------------------
#define KCHUNK 64
#define BUFSZ  16384          // 128 rows * 128 bytes
#define STAGE  32768          // A + B buffer per stage
#define NSTG   3
#define SWZOFF(row, seg) ((uint32_t)((row) * 128 + (((seg) ^ ((row) & 7)) << 4)))

__global__ __launch_bounds__(128, 2) void ctile_kernel() {
    extern __shared__ unsigned char smem[];
    const int loss = blockIdx.y;
    int t = blockIdx.x;
    int bi = 0;
    while (t >= 32 - bi) { t -= 32 - bi; bi++; }
    const int bj = bi + t;
    const int r0 = bi * 128, c0 = bj * 128;
    const bool diag = (bi == bj);
    const int tid = threadIdx.x, wid = tid >> 5, lane = tid & 31;
    const int wm = wid & 1, wn = wid >> 1;       // 2x2 warps of 64x64

    const __nv_bfloat16* ZA = g_zhi + (size_t)c_cpA[loss] * BB * DD;
    const __nv_bfloat16* ZB = g_zhi + (size_t)c_cpB[loss] * BB * DD;
    const __nv_bfloat16* sA = (r0 < BB) ? ZA + (size_t)r0 * DD : ZB + (size_t)(r0 - BB) * DD;
    const __nv_bfloat16* sB = (c0 < BB) ? ZA + (size_t)c0 * DD : ZB + (size_t)(c0 - BB) * DD;

    const uint32_t sbase = smem_u32(smem);

    float acc[4][8][4];
#pragma unroll
    for (int s = 0; s < 4; s++)
#pragma unroll
        for (int j = 0; j < 8; j++)
#pragma unroll
            for (int g = 0; g < 4; g++) acc[s][j][g] = 0.0f;

    // ---- prologue: prefetch chunks 0 and 1 into stages 0,1 ----
#pragma unroll
    for (int pc = 0; pc < 2; pc++) {
        const int kc = pc * KCHUNK;
        const uint32_t dbuf = sbase + pc * STAGE;
#pragma unroll
        for (int q = tid; q < 1024; q += 128) {
            int row = q >> 3, seg = q & 7;
            uint32_t off = SWZOFF(row, seg);
            cpasync16(dbuf + off,         sA + (size_t)row * DD + kc + seg * 8);
            cpasync16(dbuf + BUFSZ + off, sB + (size_t)row * DD + kc + seg * 8);
        }
        asm volatile("cp.async.commit_group;" ::: "memory");
    }

    uint32_t stg = 0;   // stage index of chunk c
    for (int c = 0; c < 8; c++) {
        if (c < 7) {
            asm volatile("cp.async.wait_group 1;" ::: "memory");
        } else {
            asm volatile("cp.async.wait_group 0;" ::: "memory");
        }
        __syncthreads();   // stage c visible to all; reads of stage c-1 done

        if (c < 6) {
            const int kc = (c + 2) * KCHUNK;
            uint32_t ds = stg + 2; if (ds >= NSTG) ds -= NSTG;
            const uint32_t dbuf = sbase + ds * STAGE;
#pragma unroll
            for (int q = tid; q < 1024; q += 128) {
                int row = q >> 3, seg = q & 7;
                uint32_t off = SWZOFF(row, seg);
                cpasync16(dbuf + off,         sA + (size_t)row * DD + kc + seg * 8);
                cpasync16(dbuf + BUFSZ + off, sB + (size_t)row * DD + kc + seg * 8);
            }
            asm volatile("cp.async.commit_group;" ::: "memory");
        }

        const uint32_t ab = sbase + stg * STAGE;
        const uint32_t bb = ab + BUFSZ;
#pragma unroll
        for (int kb = 0; kb < 4; kb++) {
            uint32_t af[4][4], bf[4][4];
#pragma unroll
            for (int s = 0; s < 4; s++) {
                int row = wm * 64 + s * 16 + (lane & 15);
                int seg = kb * 2 + (lane >> 4);
                ldsm4(af[s], ab + SWZOFF(row, seg));
            }
#pragma unroll
            for (int p = 0; p < 4; p++) {
                int row = wn * 64 + p * 16 + (lane & 7) + ((lane >> 4) << 3);
                int seg = kb * 2 + ((lane >> 3) & 1);
                ldsm4(bf[p], bb + SWZOFF(row, seg));
            }
#pragma unroll
            for (int s = 0; s < 4; s++)
#pragma unroll
                for (int j = 0; j < 8; j++)
                    mma16816(acc[s][j], af[s], bf[j >> 1][(j & 1) * 2],
                             bf[j >> 1][(j & 1) * 2 + 1]);
        }
        if (++stg >= NSTG) stg = 0;
    }

    // --------------------------- epilogue ---------------------------
    // acc == sim * TINV * log2(e); exp(sim/T) = ex2(acc)
    const int rl  = lane >> 2;          // row within 8-group
    const int cl2 = (lane & 3) * 2;     // col pair base
    const bool diagW = diag && (wm == wn);   // warp covers diag sub-block

    // pos capture: tiles where column block = row block + BB hold the
    // positive-pair entries on their local diagonal.
    if (c0 == r0 + BB && wm == wn) {
#pragma unroll
        for (int s = 0; s < 4; s++)
#pragma unroll
            for (int j = 0; j < 8; j++)
#pragma unroll
                for (int g = 0; g < 4; g++) {
                    int R_ = wm * 64 + s * 16 + rl + ((g >> 1) << 3);
                    int C_ = wn * 64 + j * 8 + cl2 + (g & 1);
                    if (R_ == C_) g_pos[loss * BB + r0 + R_] = acc[s][j][g];
                }
    }

    float rp[8], cp[16];

    if (!diagW) {
        __half2 rs01[4], rs23[4], csm[8];
#pragma unroll
        for (int i = 0; i < 4; i++) {
            rs01[i] = __float2half2_rn(0.0f);
            rs23[i] = __float2half2_rn(0.0f);
        }
#pragma unroll
        for (int i = 0; i < 8; i++) csm[i] = __float2half2_rn(0.0f);
#pragma unroll
        for (int s = 0; s < 4; s++)
#pragma unroll
            for (int j = 0; j < 8; j++) {
                __half2 e01 = h2exp2(__floats2half2_rn(acc[s][j][0], acc[s][j][1]));
                __half2 e23 = h2exp2(__floats2half2_rn(acc[s][j][2], acc[s][j][3]));
                rs01[s] = __hadd2(rs01[s], e01);
                rs23[s] = __hadd2(rs23[s], e23);
                csm[j]  = __hadd2(csm[j], __hadd2(e01, e23));
            }
#pragma unroll
        for (int s = 0; s < 4; s++) {
            rp[s * 2]     = __low2float(rs01[s]) + __high2float(rs01[s]);
            rp[s * 2 + 1] = __low2float(rs23[s]) + __high2float(rs23[s]);
        }
#pragma unroll
        for (int j = 0; j < 8; j++) {
            cp[j * 2]     = __low2float(csm[j]);
            cp[j * 2 + 1] = __high2float(csm[j]);
        }
    } else {
        const int rbase = r0 + wm * 64;
        const int cbase = c0 + wn * 64;
#pragma unroll
        for (int i = 0; i < 8; i++) rp[i] = 0.0f;
#pragma unroll
        for (int i = 0; i < 16; i++) cp[i] = 0.0f;
#pragma unroll
        for (int s = 0; s < 4; s++)
#pragma unroll
            for (int j = 0; j < 8; j++)
#pragma unroll
                for (int g = 0; g < 4; g++) {
                    int R = rbase + s * 16 + rl + ((g >> 1) << 3);
                    int C = cbase + j * 8 + cl2 + (g & 1);
                    float e = ex2f(acc[s][j][g]);
                    if (R == C) e = 0.0f;
                    rp[s * 2 + (g >> 1)] += e;
                    cp[j * 2 + (g & 1)]  += e;
                }
    }

#pragma unroll
    for (int i = 0; i < 8; i++) {
        rp[i] += __shfl_xor_sync(0xFFFFFFFFu, rp[i], 1);
        rp[i] += __shfl_xor_sync(0xFFFFFFFFu, rp[i], 2);
    }
#pragma unroll
    for (int i = 0; i < 16; i++) {
        cp[i] += __shfl_xor_sync(0xFFFFFFFFu, cp[i], 4);
        cp[i] += __shfl_xor_sync(0xFFFFFFFFu, cp[i], 8);
        cp[i] += __shfl_xor_sync(0xFFFFFFFFu, cp[i], 16);
    }

    // reduction buffers reuse stage-0 smem
    float* rowred = reinterpret_cast<float*>(smem);      // [2][128] (per wn)
    float* colred = rowred + 256;                        // [2][128] (per wm)
    __syncthreads();   // all warps out of mainloop before reuse
    if ((lane & 3) == 0) {
#pragma unroll
        for (int s = 0; s < 4; s++)
#pragma unroll
            for (int h = 0; h < 2; h++)
                rowred[wn * 128 + wm * 64 + s * 16 + h * 8 + rl] = rp[s * 2 + h];
    }
    if (lane < 4) {
#pragma unroll
        for (int j = 0; j < 8; j++)
#pragma unroll
            for (int b = 0; b < 2; b++)
                colred[wm * 128 + wn * 64 + j * 8 + cl2 + b] = cp[j * 2 + b];
    }
    __syncthreads();

    {
        float rs = rowred[tid] + rowred[128 + tid];
        atomicAdd(&g_rowsum[loss * NN + r0 + tid], rs);
        if (!diag) {
            float cs = colred[tid] + colred[128 + tid];
            atomicAdd(&g_rowsum[loss * NN + c0 + tid], cs);
        }
    }
}

// ---------------------------------------------------------------------------
// 3) tail kernel: ortho dots (one warp/pair-row) + element-wise finalize
//    using pos values captured by ctile.
// ---------------------------------------------------------------------------
#define ORTHO_W  (NORTHO * BB)              // 24576 ortho warp-items
#define FINW     (NLOSS * NN / 32)          // 1152 finalize warps (32 elems each)
#define TAIL_W   (ORTHO_W + FINW)           // 25728 total warps

__global__ void tail_kernel(float* out) {
    int gw   = (blockIdx.x * blockDim.x + threadIdx.x) >> 5;
    int lane = threadIdx.x & 31;
    __shared__ float red[8];
    float c = 0.0f;
    if (gw < ORTHO_W) {
        int p = gw / BB;
        int r = gw % BB;
        const __nv_bfloat16* a = g_zhi + (size_t)c_opA[p] * BB * DD + (size_t)r * DD;
        const __nv_bfloat16* b = g_zhi + (size_t)c_opB[p] * BB * DD + (size_t)r * DD;
        float d = bf16_row_dot(a, b, lane);        // = cos * SCALE_K2
        if (lane == 0) c = (1.0f - d * (1.0f / SCALE_K2)) * (1.0f / (float)BB);
    } else if (gw < TAIL_W) {
        int q    = (gw - ORTHO_W) * 32 + lane;     // 0 .. NLOSS*NN-1
        int loss = q >> 12;                        // /NN (NN=4096)
        int i    = q & (NN - 1);
        float val = logf(g_rowsum[q]);
        if (i < BB) val -= 2.0f * LN2 * g_pos[loss * BB + i];  // pos_i == pos_{i+B}
        c = val * (1.0f / (float)NN);
    }
#pragma unroll
    for (int o = 16; o; o >>= 1) c += __shfl_xor_sync(0xFFFFFFFFu, c, o);
    if (lane == 0) red[threadIdx.x >> 5] = c;
    __syncthreads();
    if (threadIdx.x < 8) {
        float v = red[threadIdx.x];
#pragma unroll
        for (int o = 4; o; o >>= 1) v += __shfl_xor_sync(0xFFu, v, o);
        if (threadIdx.x == 0) atomicAdd(out, v);
    }
}

// ---------------------------------------------------------------------------
extern "C" void kernel_launch(void* const* d_in, const int* in_sizes, int n_in,
                              void* d_out, int out_size) {
    (void)in_sizes; (void)n_in; (void)out_size;
    float* out = (float*)d_out;

    cudaFuncSetAttribute(ctile_kernel, cudaFuncAttributeMaxDynamicSharedMemorySize,
                         NSTG * STAGE);

    norm_kernel<<<(NHALF * BB) / 8, 256>>>(
        (const float*)d_in[0], (const float*)d_in[1], (const float*)d_in[2],
        (const float*)d_in[3], (const float*)d_in[4], (const float*)d_in[5], out);

    dim3 grid(528, NLOSS);
    ctile_kernel<<<grid, 128, NSTG * STAGE>>>();

    tail_kernel<<<TAIL_W / 8, 256>>>(out);
}

// round 15
// speedup vs baseline: 1.1898x; 1.0042x over previous
#include <cuda_runtime.h>
#include <cuda_bf16.h>
#include <cuda_fp16.h>
#include <math.h>
#include <stdint.h>

// Problem constants
#define BB 2048          // batch
#define NN 4096          // 2*B rows of z
#define DD 512           // half feature dim
#define NHALF 12         // 6 inputs x 2 halves
#define NLOSS 9          // contrastive losses
#define TINV 5.0f        // 1/temperature
// sqrt(TINV * log2(e)) folded into bf16 operands => acc = sim*TINV*log2e
#define SCALE_K  2.6857913787767947f
#define SCALE_K2 7.2134752044448170f   // TINV*log2(e)
#define LN2      0.6931471805599453f

// Scratch (device globals; no allocation allowed)
__device__ __nv_bfloat16 g_zhi[NHALF * BB * DD];   // bf16 normalized * SCALE_K
__device__ float         g_rowsum[NLOSS * NN];     // per-row sum of exp(sim/T)
__device__ float         g_pos[NLOSS * BB];        // pos sim * TINV*log2e (from ctile)

__constant__ int c_cpA[NLOSS] = {0, 0, 2, 6, 6,  8, 1, 3, 5};
__constant__ int c_cpB[NLOSS] = {2, 4, 4, 8, 10, 10, 7, 9, 11};
// remaining ortho pairs (cross-modality private-private); same-view pairs are
// computed inside norm_kernel.
#define NORTHO2 6
__constant__ int c_opA2[NORTHO2] = {1, 1, 3, 7, 7, 9};
__constant__ int c_opB2[NORTHO2] = {3, 5, 5, 9, 11, 11};

// ---------------------------------------------------------------------------
__device__ __forceinline__ uint32_t smem_u32(const void* p) {
    uint32_t a;
    asm("{ .reg .u64 t; cvta.to.shared.u64 t, %1; cvt.u32.u64 %0, t; }" : "=r"(a) : "l"(p));
    return a;
}
__device__ __forceinline__ void cpasync16(uint32_t dst, const void* src) {
    asm volatile("cp.async.cg.shared.global [%0], [%1], 16;" :: "r"(dst), "l"(src));
}
__device__ __forceinline__ void ldsm4(uint32_t* r, uint32_t addr) {
    asm volatile("ldmatrix.sync.aligned.m8n8.x4.shared.b16 {%0,%1,%2,%3}, [%4];"
                 : "=r"(r[0]), "=r"(r[1]), "=r"(r[2]), "=r"(r[3]) : "r"(addr));
}
__device__ __forceinline__ void mma16816(float* d, const uint32_t* a,
                                         uint32_t b0, uint32_t b1) {
    asm volatile(
        "mma.sync.aligned.m16n8k16.row.col.f32.bf16.bf16.f32 "
        "{%0,%1,%2,%3}, {%4,%5,%6,%7}, {%8,%9}, {%0,%1,%2,%3};"
        : "+f"(d[0]), "+f"(d[1]), "+f"(d[2]), "+f"(d[3])
        : "r"(a[0]), "r"(a[1]), "r"(a[2]), "r"(a[3]), "r"(b0), "r"(b1));
}
__device__ __forceinline__ float ex2f(float x) {
    float r;
    asm("ex2.approx.f32 %0, %1;" : "=f"(r) : "f"(x));
    return r;
}
// bf16 row dot product: full 512 elems (2 x uint4 per lane), warp-reduced.
__device__ __forceinline__ float bf16_row_dot(const __nv_bfloat16* a,
                                              const __nv_bfloat16* b, int lane) {
    float d = 0.0f;
#pragma unroll
    for (int w = 0; w < 2; w++) {
        uint4 xa = reinterpret_cast<const uint4*>(a)[lane + w * 32];
        uint4 xb = reinterpret_cast<const uint4*>(b)[lane + w * 32];
        const __nv_bfloat162* pa = reinterpret_cast<const __nv_bfloat162*>(&xa);
        const __nv_bfloat162* pb = reinterpret_cast<const __nv_bfloat162*>(&xb);
#pragma unroll
        for (int i = 0; i < 4; i++) {
            float2 fa = __bfloat1622float2(pa[i]);
            float2 fb = __bfloat1622float2(pb[i]);
            d += fa.x * fb.x + fa.y * fb.y;
        }
    }
#pragma unroll
    for (int o = 16; o; o >>= 1) d += __shfl_xor_sync(0xFFFFFFFFu, d, o);
    return d;
}

// ---------------------------------------------------------------------------
// 1) norm kernel: one warp per FULL input row (6 inputs x 2048 rows).
//    Normalizes both halves -> scaled bf16, computes the same-view ortho
//    term (shared·private, exact fp32) inline, zeroes rowsum + out.
// ---------------------------------------------------------------------------
__global__ void norm_kernel(const float* __restrict__ i0, const float* __restrict__ i1,
                            const float* __restrict__ i2, const float* __restrict__ i3,
                            const float* __restrict__ i4, const float* __restrict__ i5,
                            float* out) {
    int gidx = blockIdx.x * blockDim.x + threadIdx.x;
    if (gidx < NLOSS * NN) g_rowsum[gidx] = 0.0f;
    if (gidx == 0) out[0] = 0.0f;

    int gw   = gidx >> 5;
    int lane = threadIdx.x & 31;
    __shared__ float red[8];
    float c = 0.0f;

    if (gw < 6 * BB) {
        int m = gw / BB;
        int r = gw % BB;
        const float* base = (m == 0) ? i0 : (m == 1) ? i1 : (m == 2) ? i2
                           : (m == 3) ? i3 : (m == 4) ? i4 : i5;
        const float* src = base + (size_t)r * 1024;

        float4 v[8];
        float ss_s = 0.0f, ss_p = 0.0f, dt = 0.0f;
#pragma unroll
        for (int w = 0; w < 8; w++) {
            v[w] = reinterpret_cast<const float4*>(src)[lane + w * 32];
            float q = v[w].x * v[w].x + v[w].y * v[w].y + v[w].z * v[w].z + v[w].w * v[w].w;
            if (w < 4) ss_s += q; else ss_p += q;
        }
#pragma unroll
        for (int w = 0; w < 4; w++)
            dt += v[w].x * v[w + 4].x + v[w].y * v[w + 4].y
                + v[w].z * v[w + 4].z + v[w].w * v[w + 4].w;
#pragma unroll
        for (int o = 16; o; o >>= 1) {
            ss_s += __shfl_xor_sync(0xFFFFFFFFu, ss_s, o);
            ss_p += __shfl_xor_sync(0xFFFFFFFFu, ss_p, o);
            dt   += __shfl_xor_sync(0xFFFFFFFFu, dt,   o);
        }
        float inv_s = 1.0f / fmaxf(sqrtf(ss_s), 1e-8f);
        float inv_p = 1.0f / fmaxf(sqrtf(ss_p), 1e-8f);
        float ks = inv_s * SCALE_K, kp = inv_p * SCALE_K;

        __nv_bfloat162* ds = reinterpret_cast<__nv_bfloat162*>(
            g_zhi + (size_t)(2 * m) * BB * DD + (size_t)r * DD);
        __nv_bfloat162* dp = reinterpret_cast<__nv_bfloat162*>(
            g_zhi + (size_t)(2 * m + 1) * BB * DD + (size_t)r * DD);
#pragma unroll
        for (int w = 0; w < 4; w++) {
            int pi = (lane + w * 32) * 2;
            ds[pi]     = __floats2bfloat162_rn(v[w].x * ks, v[w].y * ks);
            ds[pi + 1] = __floats2bfloat162_rn(v[w].z * ks, v[w].w * ks);
            dp[pi]     = __floats2bfloat162_rn(v[w + 4].x * kp, v[w + 4].y * kp);
            dp[pi + 1] = __floats2bfloat162_rn(v[w + 4].z * kp, v[w + 4].w * kp);
        }
        // same-view ortho term: (1 - cos(shared, private)) / BB
        if (lane == 0) c = (1.0f - dt * inv_s * inv_p) * (1.0f / (float)BB);
    }
#pragma unroll
    for (int o = 16; o; o >>= 1) c += __shfl_xor_sync(0xFFFFFFFFu, c, o);
    if (lane == 0) red[threadIdx.x >> 5] = c;
    __syncthreads();
    if (threadIdx.x < 8) {
        float v = red[threadIdx.x];
#pragma unroll
        for (int o = 4; o; o >>= 1) v += __shfl_xor_sync(0xFFu, v, o);
        if (threadIdx.x == 0) atomicAdd(out, v);
    }
}

// ---------------------------------------------------------------------------
// 2) bf16 HMMA tile kernel: 128x128 sim tile, ex2 epilogue (acc pre-scaled).
//    4 warps, 64x64 warp tiles, occ 2, 3-stage cp.async pipeline,
//    fragment double-buffering inside the kb loop.
// ---------------------------------------------------------------------------
#define KCHUNK 64
#define BUFSZ  16384          // 128 rows * 128 bytes
#define STAGE  32768          // A + B buffer per stage
#define NSTG   3
#define SWZOFF(row, seg) ((uint32_t)((row) * 128 + (((seg) ^ ((row) & 7)) << 4)))

#define LOAD_FRAGS(kb, AF, BF) do {                                        \
    _Pragma("unroll")                                                      \
    for (int s_ = 0; s_ < 4; s_++) {                                       \
        int row_ = wm * 64 + s_ * 16 + (lane & 15);                        \
        int seg_ = (kb) * 2 + (lane >> 4);                                 \
        ldsm4((AF)[s_], ab + SWZOFF(row_, seg_));                          \
    }                                                                      \
    _Pragma("unroll")                                                      \
    for (int p_ = 0; p_ < 4; p_++) {                                       \
        int row_ = wn * 64 + p_ * 16 + (lane & 7) + ((lane >> 4) << 3);    \
        int seg_ = (kb) * 2 + ((lane >> 3) & 1);                           \
        ldsm4((BF)[p_], bb + SWZOFF(row_, seg_));                          \
    }                                                                      \
} while (0)

__global__ __launch_bounds__(128, 2) void ctile_kernel() {
    extern __shared__ unsigned char smem[];
    const int loss = blockIdx.y;
    int t = blockIdx.x;
    int bi = 0;
    while (t >= 32 - bi) { t -= 32 - bi; bi++; }
    const int bj = bi + t;
    const int r0 = bi * 128, c0 = bj * 128;
    const bool diag = (bi == bj);
    const int tid = threadIdx.x, wid = tid >> 5, lane = tid & 31;
    const int wm = wid & 1, wn = wid >> 1;       // 2x2 warps of 64x64

    const __nv_bfloat16* ZA = g_zhi + (size_t)c_cpA[loss] * BB * DD;
    const __nv_bfloat16* ZB = g_zhi + (size_t)c_cpB[loss] * BB * DD;
    const __nv_bfloat16* sA = (r0 < BB) ? ZA + (size_t)r0 * DD : ZB + (size_t)(r0 - BB) * DD;
    const __nv_bfloat16* sB = (c0 < BB) ? ZA + (size_t)c0 * DD : ZB + (size_t)(c0 - BB) * DD;

    const uint32_t sbase = smem_u32(smem);

    float acc[4][8][4];
#pragma unroll
    for (int s = 0; s < 4; s++)
#pragma unroll
        for (int j = 0; j < 8; j++)
#pragma unroll
            for (int g = 0; g < 4; g++) acc[s][j][g] = 0.0f;

    // ---- prologue: prefetch chunks 0 and 1 into stages 0,1 ----
#pragma unroll
    for (int pc = 0; pc < 2; pc++) {
        const int kc = pc * KCHUNK;
        const uint32_t dbuf = sbase + pc * STAGE;
#pragma unroll
        for (int q = tid; q < 1024; q += 128) {
            int row = q >> 3, seg = q & 7;
            uint32_t off = SWZOFF(row, seg);
            cpasync16(dbuf + off,         sA + (size_t)row * DD + kc + seg * 8);
            cpasync16(dbuf + BUFSZ + off, sB + (size_t)row * DD + kc + seg * 8);
        }
        asm volatile("cp.async.commit_group;" ::: "memory");
    }

    uint32_t stg = 0;   // stage index of chunk c
    for (int c = 0; c < 8; c++) {
        if (c < 7) {
            asm volatile("cp.async.wait_group 1;" ::: "memory");
        } else {
            asm volatile("cp.async.wait_group 0;" ::: "memory");
        }
        __syncthreads();   // stage c visible to all; reads of stage c-1 done

        if (c < 6) {
            const int kc = (c + 2) * KCHUNK;
            uint32_t ds = stg + 2; if (ds >= NSTG) ds -= NSTG;
            const uint32_t dbuf = sbase + ds * STAGE;
#pragma unroll
            for (int q = tid; q < 1024; q += 128) {
                int row = q >> 3, seg = q & 7;
                uint32_t off = SWZOFF(row, seg);
                cpasync16(dbuf + off,         sA + (size_t)row * DD + kc + seg * 8);
                cpasync16(dbuf + BUFSZ + off, sB + (size_t)row * DD + kc + seg * 8);
            }
            asm volatile("cp.async.commit_group;" ::: "memory");
        }

        const uint32_t ab = sbase + stg * STAGE;
        const uint32_t bb = ab + BUFSZ;

        uint32_t afr[2][4][4], bfr[2][4][4];
        LOAD_FRAGS(0, afr[0], bfr[0]);
#pragma unroll
        for (int kb = 0; kb < 4; kb++) {
            if (kb < 3) LOAD_FRAGS(kb + 1, afr[(kb + 1) & 1], bfr[(kb + 1) & 1]);
            const uint32_t (*af)[4] = afr[kb & 1];
            const uint32_t (*bf)[4] = bfr[kb & 1];
#pragma unroll
            for (int s = 0; s < 4; s++)
#pragma unroll
                for (int j = 0; j < 8; j++)
                    mma16816(acc[s][j], af[s], bf[j >> 1][(j & 1) * 2],
                             bf[j >> 1][(j & 1) * 2 + 1]);
        }
        if (++stg >= NSTG) stg = 0;
    }

    // --------------------------- epilogue ---------------------------
    // acc == sim * TINV * log2(e); exp(sim/T) = ex2(acc)
    const int rl  = lane >> 2;          // row within 8-group
    const int cl2 = (lane & 3) * 2;     // col pair base
    const bool diagW = diag && (wm == wn);   // warp covers diag sub-block

    // pos capture: tiles where column block = row block + BB hold the
    // positive-pair entries on their local diagonal.
    if (c0 == r0 + BB && wm == wn) {
#pragma unroll
        for (int s = 0; s < 4; s++)
#pragma unroll
            for (int j = 0; j < 8; j++)
#pragma unroll
                for (int g = 0; g < 4; g++) {
                    int R_ = wm * 64 + s * 16 + rl + ((g >> 1) << 3);
                    int C_ = wn * 64 + j * 8 + cl2 + (g & 1);
                    if (R_ == C_) g_pos[loss * BB + r0 + R_] = acc[s][j][g];
                }
    }

    float rp[8], cp[16];

    if (!diagW) {
        __half2 rs01[4], rs23[4], csm[8];
#pragma unroll
        for (int i = 0; i < 4; i++) {
            rs01[i] = __float2half2_rn(0.0f);
            rs23[i] = __float2half2_rn(0.0f);
        }
#pragma unroll
        for (int i = 0; i < 8; i++) csm[i] = __float2half2_rn(0.0f);
#pragma unroll
        for (int s = 0; s < 4; s++)
#pragma unroll
            for (int j = 0; j < 8; j++) {
                __half2 e01 = h2exp2(__floats2half2_rn(acc[s][j][0], acc[s][j][1]));
                __half2 e23 = h2exp2(__floats2half2_rn(acc[s][j][2], acc[s][j][3]));
                rs01[s] = __hadd2(rs01[s], e01);
                rs23[s] = __hadd2(rs23[s], e23);
                csm[j]  = __hadd2(csm[j], __hadd2(e01, e23));
            }
#pragma unroll
        for (int s = 0; s < 4; s++) {
            rp[s * 2]     = __low2float(rs01[s]) + __high2float(rs01[s]);
            rp[s * 2 + 1] = __low2float(rs23[s]) + __high2float(rs23[s]);
        }
#pragma unroll
        for (int j = 0; j < 8; j++) {
            cp[j * 2]     = __low2float(csm[j]);
            cp[j * 2 + 1] = __high2float(csm[j]);
        }
    } else {
        const int rbase = r0 + wm * 64;
        const int cbase = c0 + wn * 64;
#pragma unroll
        for (int i = 0; i < 8; i++) rp[i] = 0.0f;
#pragma unroll
        for (int i = 0; i < 16; i++) cp[i] = 0.0f;
#pragma unroll
        for (int s = 0; s < 4; s++)
#pragma unroll
            for (int j = 0; j < 8; j++)
#pragma unroll
                for (int g = 0; g < 4; g++) {
                    int R = rbase + s * 16 + rl + ((g >> 1) << 3);
                    int C = cbase + j * 8 + cl2 + (g & 1);
                    float e = ex2f(acc[s][j][g]);
                    if (R == C) e = 0.0f;
                    rp[s * 2 + (g >> 1)] += e;
                    cp[j * 2 + (g & 1)]  += e;
                }
    }

#pragma unroll
    for (int i = 0; i < 8; i++) {
        rp[i] += __shfl_xor_sync(0xFFFFFFFFu, rp[i], 1);
        rp[i] += __shfl_xor_sync(0xFFFFFFFFu, rp[i], 2);
    }
#pragma unroll
    for (int i = 0; i < 16; i++) {
        cp[i] += __shfl_xor_sync(0xFFFFFFFFu, cp[i], 4);
        cp[i] += __shfl_xor_sync(0xFFFFFFFFu, cp[i], 8);
        cp[i] += __shfl_xor_sync(0xFFFFFFFFu, cp[i], 16);
    }

    // reduction buffers reuse stage-0 smem
    float* rowred = reinterpret_cast<float*>(smem);      // [2][128] (per wn)
    float* colred = rowred + 256;                        // [2][128] (per wm)
    __syncthreads();   // all warps out of mainloop before reuse
    if ((lane & 3) == 0) {
#pragma unroll
        for (int s = 0; s < 4; s++)
#pragma unroll
            for (int h = 0; h < 2; h++)
                rowred[wn * 128 + wm * 64 + s * 16 + h * 8 + rl] = rp[s * 2 + h];
    }
    if (lane < 4) {
#pragma unroll
        for (int j = 0; j < 8; j++)
#pragma unroll
            for (int b = 0; b < 2; b++)
                colred[wm * 128 + wn * 64 + j * 8 + cl2 + b] = cp[j * 2 + b];
    }
    __syncthreads();

    {
        float rs = rowred[tid] + rowred[128 + tid];
        atomicAdd(&g_rowsum[loss * NN + r0 + tid], rs);
        if (!diag) {
            float cs = colred[tid] + colred[128 + tid];
            atomicAdd(&g_rowsum[loss * NN + c0 + tid], cs);
        }
    }
}

// ---------------------------------------------------------------------------
// 3) tail kernel: remaining ortho dots (cross-modality private pairs) +
//    element-wise finalize using pos values captured by ctile.
// ---------------------------------------------------------------------------
#define ORTHO_W  (NORTHO2 * BB)             // 12288 ortho warp-items
#define FINW     (NLOSS * NN / 32)          // 1152 finalize warps (32 elems each)
#define TAIL_W   (ORTHO_W + FINW)           // 13440 total warps

__global__ void tail_kernel(float* out) {
    int gw   = (blockIdx.x * blockDim.x + threadIdx.x) >> 5;
    int lane = threadIdx.x & 31;
    __shared__ float red[8];
    float c = 0.0f;
    if (gw < ORTHO_W) {
        int p = gw / BB;
        int r = gw % BB;
        const __nv_bfloat16* a = g_zhi + (size_t)c_opA2[p] * BB * DD + (size_t)r * DD;
        const __nv_bfloat16* b = g_zhi + (size_t)c_opB2[p] * BB * DD + (size_t)r * DD;
        float d = bf16_row_dot(a, b, lane);        // = cos * SCALE_K2
        if (lane == 0) c = (1.0f - d * (1.0f / SCALE_K2)) * (1.0f / (float)BB);
    } else if (gw < TAIL_W) {
        int q    = (gw - ORTHO_W) * 32 + lane;     // 0 .. NLOSS*NN-1
        int loss = q >> 12;                        // /NN (NN=4096)
        int i    = q & (NN - 1);
        float val = logf(g_rowsum[q]);
        if (i < BB) val -= 2.0f * LN2 * g_pos[loss * BB + i];  // pos_i == pos_{i+B}
        c = val * (1.0f / (float)NN);
    }
#pragma unroll
    for (int o = 16; o; o >>= 1) c += __shfl_xor_sync(0xFFFFFFFFu, c, o);
    if (lane == 0) red[threadIdx.x >> 5] = c;
    __syncthreads();
    if (threadIdx.x < 8) {
        float v = red[threadIdx.x];
#pragma unroll
        for (int o = 4; o; o >>= 1) v += __shfl_xor_sync(0xFFu, v, o);
        if (threadIdx.x == 0) atomicAdd(out, v);
    }
}

// ---------------------------------------------------------------------------
extern "C" void kernel_launch(void* const* d_in, const int* in_sizes, int n_in,
                              void* d_out, int out_size) {
    (void)in_sizes; (void)n_in; (void)out_size;
    float* out = (float*)d_out;

    cudaFuncSetAttribute(ctile_kernel, cudaFuncAttributeMaxDynamicSharedMemorySize,
                         NSTG * STAGE);

    norm_kernel<<<(6 * BB) / 8, 256>>>(
        (const float*)d_in[0], (const float*)d_in[1], (const float*)d_in[2],
        (const float*)d_in[3], (const float*)d_in[4], (const float*)d_in[5], out);

    dim3 grid(528, NLOSS);
    ctile_kernel<<<grid, 128, NSTG * STAGE>>>();

    tail_kernel<<<TAIL_W / 8, 256>>>(out);
}

// round 16
// speedup vs baseline: 1.4077x; 1.1832x over previous
#include <cuda_runtime.h>
#include <cuda_bf16.h>
#include <cuda_fp16.h>
#include <math.h>
#include <stdint.h>

// Problem constants
#define BB 2048          // batch
#define NN 4096          // 2*B rows of z
#define DD 512           // half feature dim
#define NHALF 12         // 6 inputs x 2 halves
#define NLOSS 9          // contrastive losses
#define TINV 5.0f        // 1/temperature
// sqrt(TINV * log2(e)) folded into bf16 operands => acc = sim*TINV*log2e
#define SCALE_K  2.6857913787767947f
#define SCALE_K2 7.2134752044448170f   // TINV*log2(e)
#define LN2      0.6931471805599453f

// Scratch (device globals; no allocation allowed)
__device__ __nv_bfloat16 g_zhi[NHALF * BB * DD];   // bf16 normalized * SCALE_K
__device__ float         g_rowsum[NLOSS * NN];     // per-row sum of exp(sim/T)
__device__ float         g_pos[NLOSS * BB];        // pos sim * TINV*log2e (from ctile)

__constant__ int c_cpA[NLOSS] = {0, 0, 2, 6, 6,  8, 1, 3, 5};
__constant__ int c_cpB[NLOSS] = {2, 4, 4, 8, 10, 10, 7, 9, 11};
// remaining ortho pairs (cross-modality private-private)
#define NORTHO2 6
__constant__ int c_opA2[NORTHO2] = {1, 1, 3, 7, 7, 9};
__constant__ int c_opB2[NORTHO2] = {3, 5, 5, 9, 11, 11};

// self-gram scatter targets: half h feeds rowsums of c_dgN[h] losses,
// at side offset c_dgS (0 = rows 0..BB-1 of that loss, 1 = rows BB..NN-1).
__constant__ int c_dgN[NHALF]     = {2, 1, 2, 1, 2, 1, 2, 1, 2, 1, 2, 1};
__constant__ int c_dgL[NHALF * 2] = {0,1, 6,6, 0,2, 7,7, 1,2, 8,8,
                                     3,4, 6,6, 3,5, 7,7, 4,5, 8,8};
__constant__ int c_dgS[NHALF * 2] = {0,0, 0,0, 1,0, 0,0, 1,1, 0,0,
                                     0,0, 1,1, 1,0, 1,1, 1,1, 1,1};

// job space: 12 self-grams x 136 upper-tri tiles, then 9 cross x 256 tiles
#define NDIAGJ  (12 * 136)     // 1632
#define NJOBS   (NDIAGJ + 9 * 256)   // 3936

// ---------------------------------------------------------------------------
__device__ __forceinline__ uint32_t smem_u32(const void* p) {
    uint32_t a;
    asm("{ .reg .u64 t; cvta.to.shared.u64 t, %1; cvt.u32.u64 %0, t; }" : "=r"(a) : "l"(p));
    return a;
}
__device__ __forceinline__ void cpasync16(uint32_t dst, const void* src) {
    asm volatile("cp.async.cg.shared.global [%0], [%1], 16;" :: "r"(dst), "l"(src));
}
__device__ __forceinline__ void ldsm4(uint32_t* r, uint32_t addr) {
    asm volatile("ldmatrix.sync.aligned.m8n8.x4.shared.b16 {%0,%1,%2,%3}, [%4];"
                 : "=r"(r[0]), "=r"(r[1]), "=r"(r[2]), "=r"(r[3]) : "r"(addr));
}
__device__ __forceinline__ void mma16816(float* d, const uint32_t* a,
                                         uint32_t b0, uint32_t b1) {
    asm volatile(
        "mma.sync.aligned.m16n8k16.row.col.f32.bf16.bf16.f32 "
        "{%0,%1,%2,%3}, {%4,%5,%6,%7}, {%8,%9}, {%0,%1,%2,%3};"
        : "+f"(d[0]), "+f"(d[1]), "+f"(d[2]), "+f"(d[3])
        : "r"(a[0]), "r"(a[1]), "r"(a[2]), "r"(a[3]), "r"(b0), "r"(b1));
}
__device__ __forceinline__ float ex2f(float x) {
    float r;
    asm("ex2.approx.f32 %0, %1;" : "=f"(r) : "f"(x));
    return r;
}
// bf16 row dot product: full 512 elems (2 x uint4 per lane), warp-reduced.
__device__ __forceinline__ float bf16_row_dot(const __nv_bfloat16* a,
                                              const __nv_bfloat16* b, int lane) {
    float d = 0.0f;
#pragma unroll
    for (int w = 0; w < 2; w++) {
        uint4 xa = reinterpret_cast<const uint4*>(a)[lane + w * 32];
        uint4 xb = reinterpret_cast<const uint4*>(b)[lane + w * 32];
        const __nv_bfloat162* pa = reinterpret_cast<const __nv_bfloat162*>(&xa);
        const __nv_bfloat162* pb = reinterpret_cast<const __nv_bfloat162*>(&xb);
#pragma unroll
        for (int i = 0; i < 4; i++) {
            float2 fa = __bfloat1622float2(pa[i]);
            float2 fb = __bfloat1622float2(pb[i]);
            d += fa.x * fb.x + fa.y * fb.y;
        }
    }
#pragma unroll
    for (int o = 16; o; o >>= 1) d += __shfl_xor_sync(0xFFFFFFFFu, d, o);
    return d;
}

// ---------------------------------------------------------------------------
// 1) norm kernel: one warp per FULL input row (6 inputs x 2048 rows).
//    Normalizes both halves -> scaled bf16, computes the same-view ortho
//    term (shared·private, exact fp32) inline, zeroes rowsum + out.
// ---------------------------------------------------------------------------
__global__ void norm_kernel(const float* __restrict__ i0, const float* __restrict__ i1,
                            const float* __restrict__ i2, const float* __restrict__ i3,
                            const float* __restrict__ i4, const float* __restrict__ i5,
                            float* out) {
    int gidx = blockIdx.x * blockDim.x + threadIdx.x;
    if (gidx < NLOSS * NN) g_rowsum[gidx] = 0.0f;
    if (gidx == 0) out[0] = 0.0f;

    int gw   = gidx >> 5;
    int lane = threadIdx.x & 31;
    __shared__ float red[8];
    float c = 0.0f;

    if (gw < 6 * BB) {
        int m = gw / BB;
        int r = gw % BB;
        const float* base = (m == 0) ? i0 : (m == 1) ? i1 : (m == 2) ? i2
                           : (m == 3) ? i3 : (m == 4) ? i4 : i5;
        const float* src = base + (size_t)r * 1024;

        float4 v[8];
        float ss_s = 0.0f, ss_p = 0.0f, dt = 0.0f;
#pragma unroll
        for (int w = 0; w < 8; w++) {
            v[w] = reinterpret_cast<const float4*>(src)[lane + w * 32];
            float q = v[w].x * v[w].x + v[w].y * v[w].y + v[w].z * v[w].z + v[w].w * v[w].w;
            if (w < 4) ss_s += q; else ss_p += q;
        }
#pragma unroll
        for (int w = 0; w < 4; w++)
            dt += v[w].x * v[w + 4].x + v[w].y * v[w + 4].y
                + v[w].z * v[w + 4].z + v[w].w * v[w + 4].w;
#pragma unroll
        for (int o = 16; o; o >>= 1) {
            ss_s += __shfl_xor_sync(0xFFFFFFFFu, ss_s, o);
            ss_p += __shfl_xor_sync(0xFFFFFFFFu, ss_p, o);
            dt   += __shfl_xor_sync(0xFFFFFFFFu, dt,   o);
        }
        float inv_s = 1.0f / fmaxf(sqrtf(ss_s), 1e-8f);
        float inv_p = 1.0f / fmaxf(sqrtf(ss_p), 1e-8f);
        float ks = inv_s * SCALE_K, kp = inv_p * SCALE_K;

        __nv_bfloat162* ds = reinterpret_cast<__nv_bfloat162*>(
            g_zhi + (size_t)(2 * m) * BB * DD + (size_t)r * DD);
        __nv_bfloat162* dp = reinterpret_cast<__nv_bfloat162*>(
            g_zhi + (size_t)(2 * m + 1) * BB * DD + (size_t)r * DD);
#pragma unroll
        for (int w = 0; w < 4; w++) {
            int pi = (lane + w * 32) * 2;
            ds[pi]     = __floats2bfloat162_rn(v[w].x * ks, v[w].y * ks);
            ds[pi + 1] = __floats2bfloat162_rn(v[w].z * ks, v[w].w * ks);
            dp[pi]     = __floats2bfloat162_rn(v[w + 4].x * kp, v[w + 4].y * kp);
            dp[pi + 1] = __floats2bfloat162_rn(v[w + 4].z * kp, v[w + 4].w * kp);
        }
        // same-view ortho term: (1 - cos(shared, private)) / BB
        if (lane == 0) c = (1.0f - dt * inv_s * inv_p) * (1.0f / (float)BB);
    }
#pragma unroll
    for (int o = 16; o; o >>= 1) c += __shfl_xor_sync(0xFFFFFFFFu, c, o);
    if (lane == 0) red[threadIdx.x >> 5] = c;
    __syncthreads();
    if (threadIdx.x < 8) {
        float v = red[threadIdx.x];
#pragma unroll
        for (int o = 4; o; o >>= 1) v += __shfl_xor_sync(0xFFu, v, o);
        if (threadIdx.x == 0) atomicAdd(out, v);
    }
}

// ---------------------------------------------------------------------------
// 2) bf16 HMMA tile kernel over DEDUPLICATED job space:
//    jobs [0, 1632): self-gram tiles  (half h, upper-tri (bi,bj) of 16x16),
//                    scattered to 1-2 loss rowsums per side table.
//    jobs [1632, 3936): cross tiles   (loss, bi, bj full 16x16),
//                    rows -> loss rows [0,BB), cols -> loss rows [BB,NN).
//    4 warps, 64x64 warp tiles, occ 2, 3-stage cp.async pipeline.
// ---------------------------------------------------------------------------
#define KCHUNK 64
#define BUFSZ  16384          // 128 rows * 128 bytes
#define STAGE  32768          // A + B buffer per stage
#define NSTG   3
#define SWZOFF(row, seg) ((uint32_t)((row) * 128 + (((seg) ^ ((row) & 7)) << 4)))

#define LOAD_FRAGS(kb, AF, BF) do {                                        \
    _Pragma("unroll")                                                      \
    for (int s_ = 0; s_ < 4; s_++) {                                       \
        int row_ = wm * 64 + s_ * 16 + (lane & 15);                        \
        int seg_ = (kb) * 2 + (lane >> 4);                                 \
        ldsm4((AF)[s_], ab + SWZOFF(row_, seg_));                          \
    }                                                                      \
    _Pragma("unroll")                                                      \
    for (int p_ = 0; p_ < 4; p_++) {                                       \
        int row_ = wn * 64 + p_ * 16 + (lane & 7) + ((lane >> 4) << 3);    \
        int seg_ = (kb) * 2 + ((lane >> 3) & 1);                           \
        ldsm4((BF)[p_], bb + SWZOFF(row_, seg_));                          \
    }                                                                      \
} while (0)

__global__ __launch_bounds__(128, 2) void ctile_kernel() {
    extern __shared__ unsigned char smem[];
    const int bx = blockIdx.x;
    const int tid = threadIdx.x, wid = tid >> 5, lane = tid & 31;
    const int wm = wid & 1, wn = wid >> 1;       // 2x2 warps of 64x64

    // ---- job decode ----
    int bi, bj;
    bool isDiag;                 // self-gram job?
    int nT;                      // number of rowsum scatter targets
    int rbase0, rbase1;          // rowsum base for row sums (target 0/1)
    int cbase0, cbase1;          // rowsum base for col sums
    int posLoss = -1;            // cross bi==bj: capture pos for this loss
    const __nv_bfloat16 *sA, *sB;

    if (bx < NDIAGJ) {
        isDiag = true;
        int h = bx / 136;
        int t = bx % 136;
        bi = 0;
        while (t >= 16 - bi) { t -= 16 - bi; bi++; }
        bj = bi + t;
        const __nv_bfloat16* Z = g_zhi + (size_t)h * BB * DD;
        sA = Z + (size_t)(bi * 128) * DD;
        sB = Z + (size_t)(bj * 128) * DD;
        nT = c_dgN[h];
        int l0 = c_dgL[h * 2],     s0 = c_dgS[h * 2];
        int l1 = c_dgL[h * 2 + 1], s1 = c_dgS[h * 2 + 1];
        rbase0 = l0 * NN + s0 * BB + bi * 128;
        cbase0 = l0 * NN + s0 * BB + bj * 128;
        rbase1 = l1 * NN + s1 * BB + bi * 128;
        cbase1 = l1 * NN + s1 * BB + bj * 128;
    } else {
        isDiag = false;
        int q = bx - NDIAGJ;
        int loss = q >> 8;
        bi = (q >> 4) & 15;
        bj = q & 15;
        sA = g_zhi + (size_t)c_cpA[loss] * BB * DD + (size_t)(bi * 128) * DD;
        sB = g_zhi + (size_t)c_cpB[loss] * BB * DD + (size_t)(bj * 128) * DD;
        nT = 1;
        rbase0 = loss * NN + bi * 128;
        cbase0 = loss * NN + BB + bj * 128;
        rbase1 = 0; cbase1 = 0;
        if (bi == bj) posLoss = loss;
    }
    const bool maskD  = isDiag && (bi == bj);   // self-sim masking needed
    const bool doCols = isDiag ? (bi < bj) : true;

    const uint32_t sbase = smem_u32(smem);

    float acc[4][8][4];
#pragma unroll
    for (int s = 0; s < 4; s++)
#pragma unroll
        for (int j = 0; j < 8; j++)
#pragma unroll
            for (int g = 0; g < 4; g++) acc[s][j][g] = 0.0f;

    // ---- prologue: prefetch chunks 0 and 1 into stages 0,1 ----
#pragma unroll
    for (int pc = 0; pc < 2; pc++) {
        const int kc = pc * KCHUNK;
        const uint32_t dbuf = sbase + pc * STAGE;
#pragma unroll
        for (int q = tid; q < 1024; q += 128) {
            int row = q >> 3, seg = q & 7;
            uint32_t off = SWZOFF(row, seg);
            cpasync16(dbuf + off,         sA + (size_t)row * DD + kc + seg * 8);
            cpasync16(dbuf + BUFSZ + off, sB + (size_t)row * DD + kc + seg * 8);
        }
        asm volatile("cp.async.commit_group;" ::: "memory");
    }

    uint32_t stg = 0;   // stage index of chunk c
    for (int c = 0; c < 8; c++) {
        if (c < 7) {
            asm volatile("cp.async.wait_group 1;" ::: "memory");
        } else {
            asm volatile("cp.async.wait_group 0;" ::: "memory");
        }
        __syncthreads();   // stage c visible to all; reads of stage c-1 done

        if (c < 6) {
            const int kc = (c + 2) * KCHUNK;
            uint32_t ds = stg + 2; if (ds >= NSTG) ds -= NSTG;
            const uint32_t dbuf = sbase + ds * STAGE;
#pragma unroll
            for (int q = tid; q < 1024; q += 128) {
                int row = q >> 3, seg = q & 7;
                uint32_t off = SWZOFF(row, seg);
                cpasync16(dbuf + off,         sA + (size_t)row * DD + kc + seg * 8);
                cpasync16(dbuf + BUFSZ + off, sB + (size_t)row * DD + kc + seg * 8);
            }
            asm volatile("cp.async.commit_group;" ::: "memory");
        }

        const uint32_t ab = sbase + stg * STAGE;
        const uint32_t bb = ab + BUFSZ;

        uint32_t afr[2][4][4], bfr[2][4][4];
        LOAD_FRAGS(0, afr[0], bfr[0]);
#pragma unroll
        for (int kb = 0; kb < 4; kb++) {
            if (kb < 3) LOAD_FRAGS(kb + 1, afr[(kb + 1) & 1], bfr[(kb + 1) & 1]);
            const uint32_t (*af)[4] = afr[kb & 1];
            const uint32_t (*bf)[4] = bfr[kb & 1];
#pragma unroll
            for (int s = 0; s < 4; s++)
#pragma unroll
                for (int j = 0; j < 8; j++)
                    mma16816(acc[s][j], af[s], bf[j >> 1][(j & 1) * 2],
                             bf[j >> 1][(j & 1) * 2 + 1]);
        }
        if (++stg >= NSTG) stg = 0;
    }

    // --------------------------- epilogue ---------------------------
    // acc == sim * TINV * log2(e); exp(sim/T) = ex2(acc)
    const int rl  = lane >> 2;          // row within 8-group
    const int cl2 = (lane & 3) * 2;     // col pair base
    const bool diagW = maskD && (wm == wn);   // warp covers masked diag

    // pos capture: cross tiles with bi==bj hold positive pairs on local diag
    if (posLoss >= 0 && wm == wn) {
#pragma unroll
        for (int s = 0; s < 4; s++)
#pragma unroll
            for (int j = 0; j < 8; j++)
#pragma unroll
                for (int g = 0; g < 4; g++) {
                    int R_ = wm * 64 + s * 16 + rl + ((g >> 1) << 3);
                    int C_ = wn * 64 + j * 8 + cl2 + (g & 1);
                    if (R_ == C_) g_pos[posLoss * BB + bi * 128 + R_] = acc[s][j][g];
                }
    }

    float rp[8], cp[16];

    if (!diagW) {
        __half2 rs01[4], rs23[4], csm[8];
#pragma unroll
        for (int i = 0; i < 4; i++) {
            rs01[i] = __float2half2_rn(0.0f);
            rs23[i] = __float2half2_rn(0.0f);
        }
#pragma unroll
        for (int i = 0; i < 8; i++) csm[i] = __float2half2_rn(0.0f);
#pragma unroll
        for (int s = 0; s < 4; s++)
#pragma unroll
            for (int j = 0; j < 8; j++) {
                __half2 e01 = h2exp2(__floats2half2_rn(acc[s][j][0], acc[s][j][1]));
                __half2 e23 = h2exp2(__floats2half2_rn(acc[s][j][2], acc[s][j][3]));
                rs01[s] = __hadd2(rs01[s], e01);
                rs23[s] = __hadd2(rs23[s], e23);
                csm[j]  = __hadd2(csm[j], __hadd2(e01, e23));
            }
#pragma unroll
        for (int s = 0; s < 4; s++) {
            rp[s * 2]     = __low2float(rs01[s]) + __high2float(rs01[s]);
            rp[s * 2 + 1] = __low2float(rs23[s]) + __high2float(rs23[s]);
        }
#pragma unroll
        for (int j = 0; j < 8; j++) {
            cp[j * 2]     = __low2float(csm[j]);
            cp[j * 2 + 1] = __high2float(csm[j]);
        }
    } else {
        // masked scalar path (self-gram diagonal warp)
#pragma unroll
        for (int i = 0; i < 8; i++) rp[i] = 0.0f;
#pragma unroll
        for (int i = 0; i < 16; i++) cp[i] = 0.0f;
#pragma unroll
        for (int s = 0; s < 4; s++)
#pragma unroll
            for (int j = 0; j < 8; j++)
#pragma unroll
                for (int g = 0; g < 4; g++) {
                    int R = wm * 64 + s * 16 + rl + ((g >> 1) << 3);
                    int C = wn * 64 + j * 8 + cl2 + (g & 1);
                    float e = ex2f(acc[s][j][g]);
                    if (R == C) e = 0.0f;     // local diag == self-sim (bi==bj)
                    rp[s * 2 + (g >> 1)] += e;
                    cp[j * 2 + (g & 1)]  += e;
                }
    }

#pragma unroll
    for (int i = 0; i < 8; i++) {
        rp[i] += __shfl_xor_sync(0xFFFFFFFFu, rp[i], 1);
        rp[i] += __shfl_xor_sync(0xFFFFFFFFu, rp[i], 2);
    }
#pragma unroll
    for (int i = 0; i < 16; i++) {
        cp[i] += __shfl_xor_sync(0xFFFFFFFFu, cp[i], 4);
        cp[i] += __shfl_xor_sync(0xFFFFFFFFu, cp[i], 8);
        cp[i] += __shfl_xor_sync(0xFFFFFFFFu, cp[i], 16);
    }

    // reduction buffers reuse stage-0 smem
    float* rowred = reinterpret_cast<float*>(smem);      // [2][128] (per wn)
    float* colred = rowred + 256;                        // [2][128] (per wm)
    __syncthreads();   // all warps out of mainloop before reuse
    if ((lane & 3) == 0) {
#pragma unroll
        for (int s = 0; s < 4; s++)
#pragma unroll
            for (int h = 0; h < 2; h++)
                rowred[wn * 128 + wm * 64 + s * 16 + h * 8 + rl] = rp[s * 2 + h];
    }
    if (lane < 4) {
#pragma unroll
        for (int j = 0; j < 8; j++)
#pragma unroll
            for (int b = 0; b < 2; b++)
                colred[wm * 128 + wn * 64 + j * 8 + cl2 + b] = cp[j * 2 + b];
    }
    __syncthreads();

    {
        float rs = rowred[tid] + rowred[128 + tid];
        atomicAdd(&g_rowsum[rbase0 + tid], rs);
        if (nT == 2) atomicAdd(&g_rowsum[rbase1 + tid], rs);
        if (doCols) {
            float cs = colred[tid] + colred[128 + tid];
            atomicAdd(&g_rowsum[cbase0 + tid], cs);
            if (nT == 2) atomicAdd(&g_rowsum[cbase1 + tid], cs);
        }
    }
}

// ---------------------------------------------------------------------------
// 3) tail kernel: remaining ortho dots (cross-modality private pairs) +
//    element-wise finalize using pos values captured by ctile.
// ---------------------------------------------------------------------------
#define ORTHO_W  (NORTHO2 * BB)             // 12288 ortho warp-items
#define FINW     (NLOSS * NN / 32)          // 1152 finalize warps (32 elems each)
#define TAIL_W   (ORTHO_W + FINW)           // 13440 total warps

__global__ void tail_kernel(float* out) {
    int gw   = (blockIdx.x * blockDim.x + threadIdx.x) >> 5;
    int lane = threadIdx.x & 31;
    __shared__ float red[8];
    float c = 0.0f;
    if (gw < ORTHO_W) {
        int p = gw / BB;
        int r = gw % BB;
        const __nv_bfloat16* a = g_zhi + (size_t)c_opA2[p] * BB * DD + (size_t)r * DD;
        const __nv_bfloat16* b = g_zhi + (size_t)c_opB2[p] * BB * DD + (size_t)r * DD;
        float d = bf16_row_dot(a, b, lane);        // = cos * SCALE_K2
        if (lane == 0) c = (1.0f - d * (1.0f / SCALE_K2)) * (1.0f / (float)BB);
    } else if (gw < TAIL_W) {
        int q    = (gw - ORTHO_W) * 32 + lane;     // 0 .. NLOSS*NN-1
        int loss = q >> 12;                        // /NN (NN=4096)
        int i    = q & (NN - 1);
        float val = logf(g_rowsum[q]);
        if (i < BB) val -= 2.0f * LN2 * g_pos[loss * BB + i];  // pos_i == pos_{i+B}
        c = val * (1.0f / (float)NN);
    }
#pragma unroll
    for (int o = 16; o; o >>= 1) c += __shfl_xor_sync(0xFFFFFFFFu, c, o);
    if (lane == 0) red[threadIdx.x >> 5] = c;
    __syncthreads();
    if (threadIdx.x < 8) {
        float v = red[threadIdx.x];
#pragma unroll
        for (int o = 4; o; o >>= 1) v += __shfl_xor_sync(0xFFu, v, o);
        if (threadIdx.x == 0) atomicAdd(out, v);
    }
}

// ---------------------------------------------------------------------------
extern "C" void kernel_launch(void* const* d_in, const int* in_sizes, int n_in,
                              void* d_out, int out_size) {
    (void)in_sizes; (void)n_in; (void)out_size;
    float* out = (float*)d_out;

    cudaFuncSetAttribute(ctile_kernel, cudaFuncAttributeMaxDynamicSharedMemorySize,
                         NSTG * STAGE);

    norm_kernel<<<(6 * BB) / 8, 256>>>(
        (const float*)d_in[0], (const float*)d_in[1], (const float*)d_in[2],
        (const float*)d_in[3], (const float*)d_in[4], (const float*)d_in[5], out);

    ctile_kernel<<<NJOBS, 128, NSTG * STAGE>>>();

    tail_kernel<<<TAIL_W / 8, 256>>>(out);
}